// round 14
// baseline (speedup 1.0000x reference)
#include <cuda_runtime.h>
#include <cuda_fp16.h>
#include <math.h>
#include <stdint.h>

// ---------------- Problem constants ----------------
#define NHEADS   128
#define DNOPE    128
#define DROPE    64
#define DQK      576
#define RKV      512
#define RQ       1536
#define HID      5120
#define QLEN     256
#define SLEN     4096
#define QB_COLS  24576
#define AO_COLS  16384
#define EPSF     1e-6f
#define NTILES_S (SLEN / 128)    // 32
#define HGRP     (NHEADS / 2)    // 64 heads per group

// ---------------- Scratch (device globals) ----------------
__device__ __align__(128) float  g_qa_buf [QLEN * RQ];
__device__ __align__(128) float  g_qfull  [QLEN * QB_COLS];
__device__ __align__(128) float  g_ckvraw [SLEN * DQK];
__device__ __align__(128) __half g_Kch    [SLEN * DQK];
__device__ __align__(128) __half g_ckvTh  [(size_t)RKV * SLEN];
__device__ __align__(128) __half g_Qch    [(size_t)NHEADS * QLEN * DQK];
__device__ __align__(128) __half g_P      [(size_t)NHEADS * QLEN * SLEN];  // 256 MB
__device__ __align__(128) __half g_och    [(size_t)NHEADS * QLEN * RKV];
__device__ __align__(128) float  g_ao     [QLEN * AO_COLS];
__device__ __align__(128) float  g_part   [8 * QLEN * HID];
__device__ __align__(128) float  g_rowm   [NHEADS * QLEN];
__device__ __align__(128) float  g_rowis  [NHEADS * QLEN];
__device__ __align__(128) float  g_tmax   [(size_t)NHEADS * QLEN * NTILES_S];
__device__ __align__(128) float  g_tsum   [(size_t)NHEADS * QLEN * NTILES_S];

// ---------------- helpers ----------------
__device__ __forceinline__ uint32_t smem_u32(const void* p) {
    uint32_t a;
    asm("{ .reg .u64 t; cvta.to.shared.u64 t, %1; cvt.u32.u64 %0, t; }" : "=r"(a) : "l"(p));
    return a;
}
__device__ __forceinline__ uint32_t f2tf(float x) {
    uint32_t r;
    asm("cvt.rna.tf32.f32 %0, %1;" : "=r"(r) : "f"(x));
    return r;
}
__device__ __forceinline__ uint32_t pack_bf16(float lo, float hi) {
    uint32_t r;
    asm("cvt.rn.bf16x2.f32 %0, %1, %2;" : "=r"(r) : "f"(hi), "f"(lo));
    return r;
}
__device__ __forceinline__ float bflo(uint32_t p) { return __uint_as_float(p << 16); }
__device__ __forceinline__ float bfhi(uint32_t p) { return __uint_as_float(p & 0xffff0000u); }

__device__ __forceinline__ void mma8(float* d, const uint32_t* a, uint32_t b0, uint32_t b1) {
    asm volatile(
        "mma.sync.aligned.m16n8k8.row.col.f32.tf32.tf32.f32 "
        "{%0,%1,%2,%3},{%4,%5,%6,%7},{%8,%9},{%0,%1,%2,%3};"
        : "+f"(d[0]), "+f"(d[1]), "+f"(d[2]), "+f"(d[3])
        : "r"(a[0]), "r"(a[1]), "r"(a[2]), "r"(a[3]), "r"(b0), "r"(b1));
}
__device__ __forceinline__ void mma16b(float* d, const uint32_t* a, uint32_t b0, uint32_t b1) {
    asm volatile(
        "mma.sync.aligned.m16n8k16.row.col.f32.bf16.bf16.f32 "
        "{%0,%1,%2,%3},{%4,%5,%6,%7},{%8,%9},{%0,%1,%2,%3};"
        : "+f"(d[0]), "+f"(d[1]), "+f"(d[2]), "+f"(d[3])
        : "r"(a[0]), "r"(a[1]), "r"(a[2]), "r"(a[3]), "r"(b0), "r"(b1));
}
__device__ __forceinline__ void mma16h(float* d, const uint32_t* a, uint32_t b0, uint32_t b1) {
    asm volatile(
        "mma.sync.aligned.m16n8k16.row.col.f32.f16.f16.f32 "
        "{%0,%1,%2,%3},{%4,%5,%6,%7},{%8,%9},{%0,%1,%2,%3};"
        : "+f"(d[0]), "+f"(d[1]), "+f"(d[2]), "+f"(d[3])
        : "r"(a[0]), "r"(a[1]), "r"(a[2]), "r"(a[3]), "r"(b0), "r"(b1));
}
__device__ __forceinline__ void ldm_x4(uint32_t* r, uint32_t addr) {
    asm volatile("ldmatrix.sync.aligned.m8n8.x4.shared.b16 {%0,%1,%2,%3}, [%4];"
                 : "=r"(r[0]), "=r"(r[1]), "=r"(r[2]), "=r"(r[3]) : "r"(addr));
}
__device__ __forceinline__ void cp16(uint32_t dst, const void* src) {
    asm volatile("cp.async.cg.shared.global [%0], [%1], 16;" :: "r"(dst), "l"(src) : "memory");
}
#define CP_COMMIT() asm volatile("cp.async.commit_group;" ::: "memory")
#define CP_WAIT(n)  asm volatile("cp.async.wait_group %0;" :: "n"(n) : "memory")

// ---------------- generic mma.sync GEMM (projections) ----------------
template<int NT, bool TRANSB, int PREC, int HOUT>
__global__ void __launch_bounds__(256, 2)
mma_gemm(const float* __restrict__ A, const float* __restrict__ B, float* __restrict__ C,
         int K, int lda, int ldb, int ldc, long sA, long sB, long sC)
{
    constexpr int BN   = NT * 32;
    constexpr int A_ST = (PREC == 0) ? 128 * 36 : 128 * 20 * 2;
    constexpr int B_ST = TRANSB ? ((PREC == 0) ? BN * 36 : BN * 20 * 2)
                                : ((PREC == 0) ? 32 * (BN + 8) : 16 * (BN + 8) * 2);
    constexpr int STG  = A_ST + B_ST;
    constexpr int BQ   = BN / 4;

    extern __shared__ uint32_t smu[];
    const uint32_t smem_base = smem_u32(smu);

    const int tid  = threadIdx.x;
    const int warp = tid >> 5;
    const int lane = tid & 31;
    const int wm = (warp >> 2) * 64;
    const int wn = (warp & 3) * (BN / 4);
    const int g  = lane >> 2;
    const int tq = lane & 3;

    const int bm = blockIdx.y * 128;
    const int bn = blockIdx.x * BN;
    A += (long)blockIdx.z * sA + (long)bm * lda;
    if (TRANSB) B += (long)blockIdx.z * sB + (long)bn * ldb;
    else        B += (long)blockIdx.z * sB + bn;
    const long coff = (long)blockIdx.z * sC + (long)bm * ldc + bn;

    const int NC = K >> 5;

    float acc[4][NT][4];
#pragma unroll
    for (int i = 0; i < 4; i++)
#pragma unroll
        for (int j = 0; j < NT; j++)
#pragma unroll
            for (int l = 0; l < 4; l++) acc[i][j][l] = 0.f;

    float4 rA[4];
    float4 rB[4];

    auto ldg_chunk = [&](int c) {
        const float* ga = A + c * 32;
#pragma unroll
        for (int i = 0; i < 4; i++) {
            int idx = tid + i * 256;
            int r = idx >> 3, c4 = (idx & 7) << 2;
            rA[i] = *(const float4*)(ga + (long)r * lda + c4);
        }
        if (TRANSB) {
            const float* gb = B + c * 32;
#pragma unroll
            for (int i = 0; i < NT; i++) {
                int idx = tid + i * 256;
                int r = idx >> 3, c4 = (idx & 7) << 2;
                rB[i] = *(const float4*)(gb + (long)r * ldb + c4);
            }
        } else if (PREC == 0) {
            const float* gb = B + (long)(c * 32) * ldb;
#pragma unroll
            for (int i = 0; i < NT; i++) {
                int idx = tid + i * 256;
                int r = idx / BQ, c4 = (idx % BQ) << 2;
                rB[i] = *(const float4*)(gb + (long)r * ldb + c4);
            }
        } else {
            const float* gb = B + (long)(c * 32) * ldb;
#pragma unroll
            for (int i = 0; i < 2; i++) {
                int u = tid + i * 256;
                if (u < 16 * BQ) {
                    int kp = u / BQ, c4 = (u % BQ) << 2;
                    rB[2 * i]     = *(const float4*)(gb + (long)(2 * kp) * ldb + c4);
                    rB[2 * i + 1] = *(const float4*)(gb + (long)(2 * kp + 1) * ldb + c4);
                }
            }
        }
    };

    auto sts_chunk = [&](int sbase) {
        uint32_t* sa = smu + sbase;
        uint32_t* sb = smu + sbase + A_ST;
        if (PREC == 0) {
#pragma unroll
            for (int i = 0; i < 4; i++) {
                int idx = tid + i * 256;
                int r = idx >> 3, c4 = (idx & 7) << 2;
                float4 v = rA[i];
                uint4 w = { f2tf(v.x), f2tf(v.y), f2tf(v.z), f2tf(v.w) };
                *(uint4*)&sa[r * 36 + c4] = w;
            }
            if (TRANSB) {
#pragma unroll
                for (int i = 0; i < NT; i++) {
                    int idx = tid + i * 256;
                    int r = idx >> 3, c4 = (idx & 7) << 2;
                    uint4 w = { f2tf(rB[i].x), f2tf(rB[i].y), f2tf(rB[i].z), f2tf(rB[i].w) };
                    *(uint4*)&sb[r * 36 + c4] = w;
                }
            } else {
#pragma unroll
                for (int i = 0; i < NT; i++) {
                    int idx = tid + i * 256;
                    int r = idx / BQ, c4 = (idx % BQ) << 2;
                    uint4 w = { f2tf(rB[i].x), f2tf(rB[i].y), f2tf(rB[i].z), f2tf(rB[i].w) };
                    *(uint4*)&sb[r * (BN + 8) + c4] = w;
                }
            }
        } else {
#pragma unroll
            for (int i = 0; i < 4; i++) {
                int idx = tid + i * 256;
                int r = idx >> 3, cu = (idx & 7) << 1;
                float4 v = rA[i];
                uint32_t h0 = pack_bf16(v.x, v.y), h1 = pack_bf16(v.z, v.w);
                uint32_t l0 = pack_bf16(v.x - bflo(h0), v.y - bfhi(h0));
                uint32_t l1 = pack_bf16(v.z - bflo(h1), v.w - bfhi(h1));
                *(uint2*)&sa[r * 20 + cu]            = make_uint2(h0, h1);
                *(uint2*)&sa[128 * 20 + r * 20 + cu] = make_uint2(l0, l1);
            }
            if (TRANSB) {
#pragma unroll
                for (int i = 0; i < NT; i++) {
                    int idx = tid + i * 256;
                    int r = idx >> 3, cu = (idx & 7) << 1;
                    float4 v = rB[i];
                    uint32_t h0 = pack_bf16(v.x, v.y), h1 = pack_bf16(v.z, v.w);
                    uint32_t l0 = pack_bf16(v.x - bflo(h0), v.y - bfhi(h0));
                    uint32_t l1 = pack_bf16(v.z - bflo(h1), v.w - bfhi(h1));
                    *(uint2*)&sb[r * 20 + cu]           = make_uint2(h0, h1);
                    *(uint2*)&sb[BN * 20 + r * 20 + cu] = make_uint2(l0, l1);
                }
            } else {
#pragma unroll
                for (int i = 0; i < 2; i++) {
                    int u = tid + i * 256;
                    if (u < 16 * BQ) {
                        int kp = u / BQ, c4 = (u % BQ) << 2;
                        float4 v0 = rB[2 * i], v1 = rB[2 * i + 1];
                        uint4 h = { pack_bf16(v0.x, v1.x), pack_bf16(v0.y, v1.y),
                                    pack_bf16(v0.z, v1.z), pack_bf16(v0.w, v1.w) };
                        uint4 l = { pack_bf16(v0.x - bflo(h.x), v1.x - bfhi(h.x)),
                                    pack_bf16(v0.y - bflo(h.y), v1.y - bfhi(h.y)),
                                    pack_bf16(v0.z - bflo(h.z), v1.z - bfhi(h.z)),
                                    pack_bf16(v0.w - bflo(h.w), v1.w - bfhi(h.w)) };
                        *(uint4*)&sb[kp * (BN + 8) + c4]                 = h;
                        *(uint4*)&sb[16 * (BN + 8) + kp * (BN + 8) + c4] = l;
                    }
                }
            }
        }
    };

    auto compute = [&](int sbase) {
        const uint32_t aB = smem_base + (uint32_t)sbase * 4;
        const uint32_t bB = smem_base + (uint32_t)(sbase + A_ST) * 4;
        const int mat = lane >> 3;
        if (PREC == 0) {
#pragma unroll
            for (int kk = 0; kk < 4; kk++) {
                const int kcu = kk * 8;
                uint32_t af[4][4];
#pragma unroll
                for (int mt = 0; mt < 4; mt++) {
                    int row = wm + mt * 16 + ((mat & 1) << 3) + (lane & 7);
                    int col = kcu + ((mat >> 1) << 2);
                    ldm_x4(af[mt], aB + (uint32_t)(row * 36 + col) * 4);
                }
                if (TRANSB) {
#pragma unroll
                    for (int np = 0; np < NT / 2; np++) {
                        uint32_t bf[4];
                        int row = wn + (2 * np + (mat >> 1)) * 8 + (lane & 7);
                        int col = kcu + ((mat & 1) << 2);
                        ldm_x4(bf, bB + (uint32_t)(row * 36 + col) * 4);
#pragma unroll
                        for (int mt = 0; mt < 4; mt++) {
                            mma8(acc[mt][2 * np],     af[mt], bf[0], bf[1]);
                            mma8(acc[mt][2 * np + 1], af[mt], bf[2], bf[3]);
                        }
                    }
                } else {
                    const uint32_t* sb = smu + sbase + A_ST;
#pragma unroll
                    for (int nt = 0; nt < NT; nt++) {
                        int n0 = wn + nt * 8 + g;
                        uint32_t b0 = sb[(kcu + tq) * (BN + 8) + n0];
                        uint32_t b1 = sb[(kcu + tq + 4) * (BN + 8) + n0];
#pragma unroll
                        for (int mt = 0; mt < 4; mt++)
                            mma8(acc[mt][nt], af[mt], b0, b1);
                    }
                }
            }
        } else {
#pragma unroll
            for (int kk = 0; kk < 2; kk++) {
                const int kcu = kk * 8;
                uint32_t ah[4][4], al[4][4];
#pragma unroll
                for (int mt = 0; mt < 4; mt++) {
                    int row = wm + mt * 16 + ((mat & 1) << 3) + (lane & 7);
                    int col = kcu + ((mat >> 1) << 2);
                    ldm_x4(ah[mt], aB + (uint32_t)(row * 20 + col) * 4);
                    ldm_x4(al[mt], aB + (uint32_t)(128 * 20 + row * 20 + col) * 4);
                }
                if (TRANSB) {
#pragma unroll
                    for (int np = 0; np < NT / 2; np++) {
                        uint32_t bh[4], bl[4];
                        int row = wn + (2 * np + (mat >> 1)) * 8 + (lane & 7);
                        int col = kcu + ((mat & 1) << 2);
                        ldm_x4(bh, bB + (uint32_t)(row * 20 + col) * 4);
                        ldm_x4(bl, bB + (uint32_t)(BN * 20 + row * 20 + col) * 4);
#pragma unroll
                        for (int mt = 0; mt < 4; mt++) {
                            mma16b(acc[mt][2 * np], ah[mt], bh[0], bh[1]);
                            mma16b(acc[mt][2 * np], al[mt], bh[0], bh[1]);
                            mma16b(acc[mt][2 * np], ah[mt], bl[0], bl[1]);
                            mma16b(acc[mt][2 * np + 1], ah[mt], bh[2], bh[3]);
                            mma16b(acc[mt][2 * np + 1], al[mt], bh[2], bh[3]);
                            mma16b(acc[mt][2 * np + 1], ah[mt], bl[2], bl[3]);
                        }
                    }
                } else {
                    const uint32_t* sbh = smu + sbase + A_ST;
                    const uint32_t* sbl = sbh + 16 * (BN + 8);
#pragma unroll
                    for (int nt = 0; nt < NT; nt++) {
                        int n0 = wn + nt * 8 + g;
                        uint32_t b0h = sbh[(kcu + tq) * (BN + 8) + n0];
                        uint32_t b1h = sbh[(kcu + tq + 4) * (BN + 8) + n0];
                        uint32_t b0l = sbl[(kcu + tq) * (BN + 8) + n0];
                        uint32_t b1l = sbl[(kcu + tq + 4) * (BN + 8) + n0];
#pragma unroll
                        for (int mt = 0; mt < 4; mt++) {
                            mma16b(acc[mt][nt], ah[mt], b0h, b1h);
                            mma16b(acc[mt][nt], al[mt], b0h, b1h);
                            mma16b(acc[mt][nt], ah[mt], b0l, b1l);
                        }
                    }
                }
            }
        }
    };

    ldg_chunk(0);
    sts_chunk(0);
    __syncthreads();
    for (int c = 0; c < NC; c++) {
        if (c + 1 < NC) ldg_chunk(c + 1);
        compute((c & 1) * STG);
        if (c + 1 < NC) {
            sts_chunk(((c + 1) & 1) * STG);
            __syncthreads();
        }
    }

    if (!HOUT) {
        float* Cf = C + coff;
#pragma unroll
        for (int mt = 0; mt < 4; mt++) {
            const int r0 = wm + mt * 16 + g;
#pragma unroll
            for (int nt = 0; nt < NT; nt++) {
                const int c0 = wn + nt * 8 + tq * 2;
                *(float2*)&Cf[(long)r0 * ldc + c0]       = make_float2(acc[mt][nt][0], acc[mt][nt][1]);
                *(float2*)&Cf[(long)(r0 + 8) * ldc + c0] = make_float2(acc[mt][nt][2], acc[mt][nt][3]);
            }
        }
    } else {
        __half* Ch = ((__half*)C) + coff;
#pragma unroll
        for (int mt = 0; mt < 4; mt++) {
            const int r0 = wm + mt * 16 + g;
#pragma unroll
            for (int nt = 0; nt < NT; nt++) {
                const int c0 = wn + nt * 8 + tq * 2;
                *(__half2*)&Ch[(long)r0 * ldc + c0]       = __floats2half2_rn(acc[mt][nt][0], acc[mt][nt][1]);
                *(__half2*)&Ch[(long)(r0 + 8) * ldc + c0] = __floats2half2_rn(acc[mt][nt][2], acc[mt][nt][3]);
            }
        }
    }
}

// ---------------- fp16 QK^T GEMM, cp.async 3-stage k64 chunks, fused exp + tile stats ----------------
__global__ void __launch_bounds__(256, 2)
qk_gemm(const __half* __restrict__ A, const __half* __restrict__ B, __half* __restrict__ Ph,
        float escale, float* __restrict__ gtmax, float* __restrict__ gtsum)
{
    constexpr int A_ST = 128 * 36;     // k64 chunk
    constexpr int B_ST = 128 * 36;
    constexpr int STG  = A_ST + B_ST;
    constexpr int NC   = DQK / 64;     // 9

    extern __shared__ uint32_t smu[];
    const uint32_t smem_base = smem_u32(smu);

    const int tid  = threadIdx.x;
    const int warp = tid >> 5;
    const int lane = tid & 31;
    const int wm = (warp >> 2) * 64;
    const int wn = (warp & 3) * 32;
    const int g  = lane >> 2;
    const int tq = lane & 3;
    const int mat = lane >> 3;

    const int bm = blockIdx.y * 128;
    const int bn = blockIdx.x * 128;
    const int z  = blockIdx.z;
    A  += (long)z * QLEN * DQK + (long)bm * DQK;
    B  += (long)bn * DQK;
    Ph += (long)z * QLEN * SLEN + (long)bm * SLEN + bn;

    float acc[4][4][4];
#pragma unroll
    for (int i = 0; i < 4; i++)
#pragma unroll
        for (int j = 0; j < 4; j++)
#pragma unroll
            for (int l = 0; l < 4; l++) acc[i][j][l] = 0.f;

    auto cp_chunk = [&](int c, int stg) {
        const uint32_t sa = smem_base + (uint32_t)(stg * STG) * 4;
        const uint32_t sb = sa + A_ST * 4;
        const __half* ga = A + c * 64;
        const __half* gb = B + c * 64;
#pragma unroll
        for (int i = 0; i < 4; i++) {
            int o = tid + i * 256;
            int r = o >> 3, cu = (o & 7) * 4;
            cp16(sa + (uint32_t)(r * 36 + cu) * 4, ga + (long)r * DQK + cu * 2);
            cp16(sb + (uint32_t)(r * 36 + cu) * 4, gb + (long)r * DQK + cu * 2);
        }
    };

    auto compute = [&](int stg) {
        const uint32_t aB = smem_base + (uint32_t)(stg * STG) * 4;
        const uint32_t bB = aB + A_ST * 4;
#pragma unroll
        for (int kk = 0; kk < 4; kk++) {
            const int kcu = kk * 8;
            uint32_t af[4][4];
#pragma unroll
            for (int mt = 0; mt < 4; mt++) {
                int row = wm + mt * 16 + ((mat & 1) << 3) + (lane & 7);
                int col = kcu + ((mat >> 1) << 2);
                ldm_x4(af[mt], aB + (uint32_t)(row * 36 + col) * 4);
            }
#pragma unroll
            for (int np = 0; np < 2; np++) {
                uint32_t bf[4];
                int row = wn + (2 * np + (mat >> 1)) * 8 + (lane & 7);
                int col = kcu + ((mat & 1) << 2);
                ldm_x4(bf, bB + (uint32_t)(row * 36 + col) * 4);
#pragma unroll
                for (int mt = 0; mt < 4; mt++) {
                    mma16h(acc[mt][2 * np],     af[mt], bf[0], bf[1]);
                    mma16h(acc[mt][2 * np + 1], af[mt], bf[2], bf[3]);
                }
            }
        }
    };

    cp_chunk(0, 0); CP_COMMIT();
    cp_chunk(1, 1); CP_COMMIT();
    for (int c = 0; c < NC; c++) {
        CP_WAIT(1);
        __syncthreads();
        if (c + 2 < NC) cp_chunk(c + 2, (c + 2) % 3);
        CP_COMMIT();
        compute(c % 3);
    }

    // stats reuse stage-0 smem (all stage reads finished; barrier below orders it)
    float* st_max = (float*)smu;
    float* st_sum = st_max + 512;
    const int nw = warp & 3;
    __syncthreads();
#pragma unroll
    for (int mt = 0; mt < 4; mt++) {
#pragma unroll
        for (int h = 0; h < 2; h++) {
            float mx = -INFINITY;
#pragma unroll
            for (int nt = 0; nt < 4; nt++) {
                mx = fmaxf(mx, acc[mt][nt][2 * h]);
                mx = fmaxf(mx, acc[mt][nt][2 * h + 1]);
            }
            mx = fmaxf(mx, __shfl_xor_sync(0xffffffffu, mx, 1));
            mx = fmaxf(mx, __shfl_xor_sync(0xffffffffu, mx, 2));
            if (tq == 0) st_max[(wm + mt * 16 + h * 8 + g) * 4 + nw] = mx * escale;
        }
    }
    __syncthreads();
#pragma unroll
    for (int mt = 0; mt < 4; mt++) {
#pragma unroll
        for (int h = 0; h < 2; h++) {
            const int row = wm + mt * 16 + h * 8 + g;
            float rm = fmaxf(fmaxf(st_max[row * 4 + 0], st_max[row * 4 + 1]),
                             fmaxf(st_max[row * 4 + 2], st_max[row * 4 + 3]));
            float s = 0.f;
#pragma unroll
            for (int nt = 0; nt < 4; nt++) {
                float p0 = __expf(fmaf(acc[mt][nt][2 * h],     escale, -rm));
                float p1 = __expf(fmaf(acc[mt][nt][2 * h + 1], escale, -rm));
                s += p0 + p1;
                *(__half2*)&Ph[(long)row * SLEN + wn + nt * 8 + tq * 2] =
                    __floats2half2_rn(p0, p1);
            }
            s += __shfl_xor_sync(0xffffffffu, s, 1);
            s += __shfl_xor_sync(0xffffffffu, s, 2);
            if (tq == 0) st_sum[row * 4 + nw] = s;
        }
    }
    __syncthreads();
    if (tid < 128) {
        float m = fmaxf(fmaxf(st_max[tid * 4 + 0], st_max[tid * 4 + 1]),
                        fmaxf(st_max[tid * 4 + 2], st_max[tid * 4 + 3]));
        float s = st_sum[tid * 4 + 0] + st_sum[tid * 4 + 1]
                + st_sum[tid * 4 + 2] + st_sum[tid * 4 + 3];
        long grow = (long)z * QLEN + bm + tid;
        gtmax[grow * NTILES_S + blockIdx.x] = m;
        gtsum[grow * NTILES_S + blockIdx.x] = s;
    }
}

// ---------------- fp16 PV GEMM, cp.async 3-stage k64 chunks, in-register rescale ----------------
__global__ void __launch_bounds__(256, 2)
pv_gemm(const __half* __restrict__ A, const __half* __restrict__ B, __half* __restrict__ C,
        const float* __restrict__ tmax, const float* __restrict__ rowm,
        const float* __restrict__ rowis)
{
    constexpr int A_ST = 128 * 36;
    constexpr int B_ST = 128 * 36;
    constexpr int STG  = A_ST + B_ST;
    constexpr int NC   = SLEN / 64;   // 64 chunks

    extern __shared__ uint32_t smu[];
    const uint32_t smem_base = smem_u32(smu);

    const int tid  = threadIdx.x;
    const int warp = tid >> 5;
    const int lane = tid & 31;
    const int wm = (warp >> 2) * 64;
    const int wn = (warp & 3) * 32;
    const int g  = lane >> 2;
    const int tq = lane & 3;
    const int mat = lane >> 3;

    const int bm = blockIdx.y * 128;
    const int bn = blockIdx.x * 128;
    const int z  = blockIdx.z;
    A += (long)z * QLEN * SLEN + (long)bm * SLEN;
    B += (long)bn * SLEN;
    C += (long)z * QLEN * RKV + (long)bm * RKV + bn;

    const long gbase = (long)z * QLEN + bm;
    float rm_[4][2], ris_[4][2];
#pragma unroll
    for (int mt = 0; mt < 4; mt++) {
        int r0 = wm + mt * 16 + g;
        rm_[mt][0]  = rowm[gbase + r0];
        rm_[mt][1]  = rowm[gbase + r0 + 8];
        ris_[mt][0] = rowis[gbase + r0];
        ris_[mt][1] = rowis[gbase + r0 + 8];
    }
    const float* tmax_b = tmax + gbase * NTILES_S;

    float acc[4][4][4];
#pragma unroll
    for (int i = 0; i < 4; i++)
#pragma unroll
        for (int j = 0; j < 4; j++)
#pragma unroll
            for (int l = 0; l < 4; l++) acc[i][j][l] = 0.f;

    uint32_t fac[4][2];

    auto upd_fac = [&](int tile) {
#pragma unroll
        for (int mt = 0; mt < 4; mt++) {
            int r0 = wm + mt * 16 + g;
            float f0 = __expf(tmax_b[(long)r0 * NTILES_S + tile] - rm_[mt][0]) * ris_[mt][0];
            float f1 = __expf(tmax_b[(long)(r0 + 8) * NTILES_S + tile] - rm_[mt][1]) * ris_[mt][1];
            __half2 h0 = __half2half2(__float2half_rn(f0));
            __half2 h1 = __half2half2(__float2half_rn(f1));
            fac[mt][0] = *(uint32_t*)&h0;
            fac[mt][1] = *(uint32_t*)&h1;
        }
    };

    auto cp_chunk = [&](int c, int stg) {
        const uint32_t sa = smem_base + (uint32_t)(stg * STG) * 4;
        const uint32_t sb = sa + A_ST * 4;
        const __half* ga = A + c * 64;
        const __half* gb = B + c * 64;
#pragma unroll
        for (int i = 0; i < 4; i++) {
            int o = tid + i * 256;
            int r = o >> 3, cu = (o & 7) * 4;
            cp16(sa + (uint32_t)(r * 36 + cu) * 4, ga + (long)r * SLEN + cu * 2);
            cp16(sb + (uint32_t)(r * 36 + cu) * 4, gb + (long)r * SLEN + cu * 2);
        }
    };

    auto compute = [&](int stg) {
        const uint32_t aB = smem_base + (uint32_t)(stg * STG) * 4;
        const uint32_t bB = aB + A_ST * 4;
#pragma unroll
        for (int kk = 0; kk < 4; kk++) {
            const int kcu = kk * 8;
            uint32_t af[4][4];
#pragma unroll
            for (int mt = 0; mt < 4; mt++) {
                int row = wm + mt * 16 + ((mat & 1) << 3) + (lane & 7);
                int col = kcu + ((mat >> 1) << 2);
                ldm_x4(af[mt], aB + (uint32_t)(row * 36 + col) * 4);
                __half2 f0 = *(__half2*)&fac[mt][0];
                __half2 f1 = *(__half2*)&fac[mt][1];
                *(__half2*)&af[mt][0] = __hmul2(*(__half2*)&af[mt][0], f0);
                *(__half2*)&af[mt][2] = __hmul2(*(__half2*)&af[mt][2], f0);
                *(__half2*)&af[mt][1] = __hmul2(*(__half2*)&af[mt][1], f1);
                *(__half2*)&af[mt][3] = __hmul2(*(__half2*)&af[mt][3], f1);
            }
#pragma unroll
            for (int np = 0; np < 2; np++) {
                uint32_t bf[4];
                int row = wn + (2 * np + (mat >> 1)) * 8 + (lane & 7);
                int col = kcu + ((mat & 1) << 2);
                ldm_x4(bf, bB + (uint32_t)(row * 36 + col) * 4);
#pragma unroll
                for (int mt = 0; mt < 4; mt++) {
                    mma16h(acc[mt][2 * np],     af[mt], bf[0], bf[1]);
                    mma16h(acc[mt][2 * np + 1], af[mt], bf[2], bf[3]);
                }
            }
        }
    };

    cp_chunk(0, 0); CP_COMMIT();
    cp_chunk(1, 1); CP_COMMIT();
    for (int c = 0; c < NC; c++) {
        CP_WAIT(1);
        __syncthreads();
        if (c + 2 < NC) cp_chunk(c + 2, (c + 2) % 3);
        CP_COMMIT();
        if ((c & 1) == 0) upd_fac(c >> 1);
        compute(c % 3);
    }

#pragma unroll
    for (int mt = 0; mt < 4; mt++) {
        const int r0 = wm + mt * 16 + g;
#pragma unroll
        for (int nt = 0; nt < 4; nt++) {
            const int c0 = wn + nt * 8 + tq * 2;
            *(__half2*)&C[(long)r0 * RKV + c0]       = __floats2half2_rn(acc[mt][nt][0], acc[mt][nt][1]);
            *(__half2*)&C[(long)(r0 + 8) * RKV + c0] = __floats2half2_rn(acc[mt][nt][2], acc[mt][nt][3]);
        }
    }
}

// ---------------- OV GEMM: ao[:, h*128:] = och[h] @ outabsorb[h]^T ----------------
__global__ void __launch_bounds__(256, 2)
ov_gemm(const __half* __restrict__ A, const float* __restrict__ B, float* __restrict__ C,
        long sB)
{
    constexpr int A_ST = 128 * 20;
    constexpr int B_ST = 2 * 128 * 20;
    constexpr int STG  = A_ST + B_ST;
    constexpr int NC   = RKV / 32;

    extern __shared__ uint32_t smu[];
    const uint32_t smem_base = smem_u32(smu);

    const int tid  = threadIdx.x;
    const int warp = tid >> 5;
    const int lane = tid & 31;
    const int wm = (warp >> 2) * 64;
    const int wn = (warp & 3) * 32;
    const int g  = lane >> 2;
    const int tq = lane & 3;
    const int mat = lane >> 3;

    const int bm = blockIdx.y * 128;
    const int z  = blockIdx.z;
    A += (long)z * QLEN * RKV + (long)bm * RKV;
    B += (long)z * sB;
    C += (long)z * DNOPE + (long)bm * AO_COLS;

    float acc[4][4][4];
#pragma unroll
    for (int i = 0; i < 4; i++)
#pragma unroll
        for (int j = 0; j < 4; j++)
#pragma unroll
            for (int l = 0; l < 4; l++) acc[i][j][l] = 0.f;

    float4 rB[4];

    auto cpA_chunk = [&](int c, int stg) {
        const uint32_t sa = smem_base + (uint32_t)(stg * STG) * 4;
        const __half* ga = A + c * 32;
#pragma unroll
        for (int i = 0; i < 2; i++) {
            int o = tid + i * 256;
            int r = o >> 2, cu = (o & 3) * 4;
            cp16(sa + (uint32_t)(r * 20 + cu) * 4, ga + (long)r * RKV + cu * 2);
        }
    };

    auto ldgB_chunk = [&](int c) {
        const float* gb = B + c * 32;
#pragma unroll
        for (int i = 0; i < 4; i++) {
            int o = tid + i * 256;
            int r = o >> 3, c4 = (o & 7) << 2;
            rB[i] = *(const float4*)(gb + (long)r * RKV + c4);
        }
    };

    auto stsB_chunk = [&](int stg) {
        uint32_t* sbh = smu + stg * STG + A_ST;
        uint32_t* sbl = sbh + 128 * 20;
#pragma unroll
        for (int i = 0; i < 4; i++) {
            int o = tid + i * 256;
            int r = o >> 3, cu = (o & 7) << 1;
            float4 v = rB[i];
            __half2 h0 = __floats2half2_rn(v.x, v.y);
            __half2 h1 = __floats2half2_rn(v.z, v.w);
            __half2 l0 = __floats2half2_rn(v.x - __half2float(h0.x), v.y - __half2float(h0.y));
            __half2 l1 = __floats2half2_rn(v.z - __half2float(h1.x), v.w - __half2float(h1.y));
            *(uint2*)&sbh[r * 20 + cu] = make_uint2(*(uint32_t*)&h0, *(uint32_t*)&h1);
            *(uint2*)&sbl[r * 20 + cu] = make_uint2(*(uint32_t*)&l0, *(uint32_t*)&l1);
        }
    };

    auto compute = [&](int stg) {
        const uint32_t aB  = smem_base + (uint32_t)(stg * STG) * 4;
        const uint32_t bBh = aB + A_ST * 4;
        const uint32_t bBl = bBh + 128 * 20 * 4;
#pragma unroll
        for (int kk = 0; kk < 2; kk++) {
            const int kcu = kk * 8;
            uint32_t af[4][4];
#pragma unroll
            for (int mt = 0; mt < 4; mt++) {
                int row = wm + mt * 16 + ((mat & 1) << 3) + (lane & 7);
                int col = kcu + ((mat >> 1) << 2);
                ldm_x4(af[mt], aB + (uint32_t)(row * 20 + col) * 4);
            }
#pragma unroll
            for (int np = 0; np < 2; np++) {
                uint32_t bh[4], bl[4];
                int row = wn + (2 * np + (mat >> 1)) * 8 + (lane & 7);
                int col = kcu + ((mat & 1) << 2);
                ldm_x4(bh, bBh + (uint32_t)(row * 20 + col) * 4);
                ldm_x4(bl, bBl + (uint32_t)(row * 20 + col) * 4);
#pragma unroll
                for (int mt = 0; mt < 4; mt++) {
                    mma16h(acc[mt][2 * np],     af[mt], bh[0], bh[1]);
                    mma16h(acc[mt][2 * np],     af[mt], bl[0], bl[1]);
                    mma16h(acc[mt][2 * np + 1], af[mt], bh[2], bh[3]);
                    mma16h(acc[mt][2 * np + 1], af[mt], bl[2], bl[3]);
                }
            }
        }
    };

    ldgB_chunk(0);
    cpA_chunk(0, 0); CP_COMMIT();
    stsB_chunk(0);
    CP_WAIT(0);
    __syncthreads();
    for (int c = 0; c < NC; c++) {
        if (c + 1 < NC) { ldgB_chunk(c + 1); cpA_chunk(c + 1, (c + 1) & 1); }
        CP_COMMIT();
        compute(c & 1);
        if (c + 1 < NC) {
            stsB_chunk((c + 1) & 1);
            CP_WAIT(0);
            __syncthreads();
        }
    }

#pragma unroll
    for (int mt = 0; mt < 4; mt++) {
        const int r0 = wm + mt * 16 + g;
#pragma unroll
        for (int nt = 0; nt < 4; nt++) {
            const int c0 = wn + nt * 8 + tq * 2;
            *(float2*)&C[(long)r0 * AO_COLS + c0]       = make_float2(acc[mt][nt][0], acc[mt][nt][1]);
            *(float2*)&C[(long)(r0 + 8) * AO_COLS + c0] = make_float2(acc[mt][nt][2], acc[mt][nt][3]);
        }
    }
}

// ---------------- Combine tile stats ----------------
__global__ void combine_stats(const float* __restrict__ tmax, const float* __restrict__ tsum,
                              float* __restrict__ rm, float* __restrict__ ris)
{
    const int row = blockIdx.x * 8 + threadIdx.y;
    const int t = threadIdx.x;
    float mv = tmax[(long)row * NTILES_S + t];
    float m = mv;
#pragma unroll
    for (int o = 16; o > 0; o >>= 1) m = fmaxf(m, __shfl_xor_sync(0xffffffffu, m, o));
    float s = tsum[(long)row * NTILES_S + t] * __expf(mv - m);
#pragma unroll
    for (int o = 16; o > 0; o >>= 1) s += __shfl_xor_sync(0xffffffffu, s, o);
    if (t == 0) { rm[row] = m; ris[row] = 1.f / s; }
}

// ---------------- Transpose half->half ----------------
__global__ void transpose_hh(const __half* __restrict__ in, __half* __restrict__ out,
                             int R, int ldin)
{
    __shared__ __half t[32][40];
    const int c0 = blockIdx.x * 32, r0 = blockIdx.y * 32;
    const int x = threadIdx.x, y0 = threadIdx.y;
    #pragma unroll
    for (int i = y0; i < 32; i += 8) t[i][x] = in[(long)(r0 + i) * ldin + c0 + x];
    __syncthreads();
    #pragma unroll
    for (int i = y0; i < 32; i += 8) out[(long)(c0 + i) * R + r0 + x] = t[x][i];
}

// ---------------- Split-K reduction ----------------
__global__ void reduce_slices(const float4* __restrict__ in, float4* __restrict__ out,
                              int n4, int S)
{
    int i = blockIdx.x * 256 + threadIdx.x;
    if (i >= n4) return;
    float4 a = in[i];
    for (int s = 1; s < S; s++) {
        float4 b = in[i + (long)s * n4];
        a.x += b.x; a.y += b.y; a.z += b.z; a.w += b.w;
    }
    out[i] = a;
}

// ---------------- Fused split-K reduce + RMSNorm for step 1 ----------------
// part: 8 slices of [QLEN, RQ]; out: qa normalized. One block per row.
__global__ void reduce_rmsnorm(const float4* __restrict__ in, float4* __restrict__ out,
                               const float* __restrict__ gw)
{
    const int row = blockIdx.x;
    const int tid = threadIdx.x;             // 256
    const int n4 = RQ / 4;                   // 384
    const int base = row * n4;
    float ss = 0.f;
    for (int c = tid; c < n4; c += 256) {
        float4 a = in[base + c];
#pragma unroll
        for (int s = 1; s < 8; s++) {
            float4 b = in[base + c + (long)s * QLEN * n4];
            a.x += b.x; a.y += b.y; a.z += b.z; a.w += b.w;
        }
        out[base + c] = a;                    // un-normalized sum
        ss += a.x * a.x + a.y * a.y + a.z * a.z + a.w * a.w;
    }
    __shared__ float red[256];
    red[tid] = ss; __syncthreads();
    for (int s = 128; s > 0; s >>= 1) { if (tid < s) red[tid] += red[tid + s]; __syncthreads(); }
    const float inv = rsqrtf(red[0] / (float)RQ + EPSF);
    for (int c = tid; c < n4; c += 256) {
        float4 v = out[base + c];
        float4 w = ((const float4*)gw)[c];
        v.x *= inv * w.x; v.y *= inv * w.y; v.z *= inv * w.z; v.w *= inv * w.w;
        out[base + c] = v;
    }
}

// ---------------- Build K_comb -> fp16 ----------------
__global__ void build_K(const float* __restrict__ raw, const float* __restrict__ g,
                        const int* __restrict__ kvpos, __half* __restrict__ Kh)
{
    const int s = blockIdx.x;
    const float* r = raw + (long)s * DQK;
    __half* k = Kh + (long)s * DQK;
    const int tid = threadIdx.x;

    float ss = 0.f;
    for (int c = tid; c < RKV / 4; c += 128) {
        float4 v = ((const float4*)r)[c];
        ss += v.x * v.x + v.y * v.y + v.z * v.z + v.w * v.w;
    }
    __shared__ float red[128];
    red[tid] = ss; __syncthreads();
    for (int st = 64; st > 0; st >>= 1) { if (tid < st) red[tid] += red[tid + st]; __syncthreads(); }
    const float inv = rsqrtf(red[0] / (float)RKV + EPSF);
    for (int c = tid; c < RKV / 4; c += 128) {
        float4 v = ((const float4*)r)[c];
        float4 w = ((const float4*)g)[c];
        __half2 h0 = __floats2half2_rn(v.x * inv * w.x, v.y * inv * w.y);
        __half2 h1 = __floats2half2_rn(v.z * inv * w.z, v.w * inv * w.w);
        *(__half2*)&k[c * 4]     = h0;
        *(__half2*)&k[c * 4 + 2] = h1;
    }

    if (tid < 32) {
        const int j = tid;
        const float x0 = r[RKV + 2 * j];
        const float x1 = r[RKV + 2 * j + 1];
        const float pos = (float)kvpos[s];
        const float invf = powf(10000.f, -(float)j / 32.f);
        float cs, sn; sincosf(pos * invf, &sn, &cs);
        k[RKV + j]      = __float2half_rn(x0 * cs - x1 * sn);
        k[RKV + 32 + j] = __float2half_rn(x0 * sn + x1 * cs);
    }
}

// ---------------- RoPE for q_pe -> fp16 ----------------
__global__ void rope_Q(const float* __restrict__ qfull, const int* __restrict__ qpos,
                       __half* __restrict__ Qh)
{
    const int t = blockIdx.x;
    const int h = blockIdx.y;
    const int j = threadIdx.x;
    const float* src = qfull + (long)t * QB_COLS + h * (DNOPE + DROPE) + DNOPE;
    const float x0 = src[2 * j];
    const float x1 = src[2 * j + 1];
    const float pos = (float)qpos[t];
    const float invf = powf(10000.f, -(float)j / 32.f);
    float cs, sn; sincosf(pos * invf, &sn, &cs);
    __half* dst = Qh + ((long)h * QLEN + t) * DQK + RKV;
    dst[j]      = __float2half_rn(x0 * cs - x1 * sn);
    dst[32 + j] = __float2half_rn(x0 * sn + x1 * cs);
}

// ---------------- Launch ----------------
static inline void* symv(const void* s)
{
    void* p = nullptr;
    cudaGetSymbolAddress(&p, s);
    return p;
}

static inline int smem_b(int NT, bool transb, int prec)
{
    int a = (prec == 0) ? 128 * 36 : 128 * 40;
    int b = transb ? ((prec == 0) ? NT * 32 * 36 : NT * 32 * 40)
                   : 32 * (NT * 32 + 8);
    return 2 * (a + b) * 4;
}
#define SMEM_PV (3 * (128 * 36 + 128 * 36) * 4)
#define SMEM_QK (3 * (128 * 36 + 128 * 36) * 4)
#define SMEM_OV (2 * (128 * 20 + 2 * 128 * 20) * 4)

extern "C" void kernel_launch(void* const* d_in, const int* in_sizes, int n_in,
                              void* d_out, int out_size)
{
    const float* hq    = (const float*)d_in[0];
    const float* hkv   = (const float*)d_in[1];
    const float* W_qa  = (const float*)d_in[2];
    const float* gqa   = (const float*)d_in[3];
    const float* W_qb  = (const float*)d_in[4];
    const float* W_kva = (const float*)d_in[5];
    const float* gkva  = (const float*)d_in[6];
    const float* W_kvb = (const float*)d_in[7];
    const float* W_o   = (const float*)d_in[8];
    const int*   qpos  = (const int*)d_in[9];
    const int*   kvpos = (const int*)d_in[10];
    float*       out   = (float*)d_out;

    float*  qa     = (float*) symv(g_qa_buf);
    float*  qfull  = (float*) symv(g_qfull);
    float*  ckvraw = (float*) symv(g_ckvraw);
    __half* Kch    = (__half*)symv(g_Kch);
    __half* ckvTh  = (__half*)symv(g_ckvTh);
    __half* Qch    = (__half*)symv(g_Qch);
    __half* P      = (__half*)symv(g_P);
    __half* och    = (__half*)symv(g_och);
    float*  ao     = (float*) symv(g_ao);
    float*  part   = (float*) symv(g_part);
    float*  rowm   = (float*) symv(g_rowm);
    float*  rowis  = (float*) symv(g_rowis);
    float*  tmax   = (float*) symv(g_tmax);
    float*  tsum   = (float*) symv(g_tsum);

    const float scale = 1.0f / sqrtf(192.0f);

    static cudaStream_t s2 = nullptr, s3 = nullptr;
    static cudaEvent_t evF = nullptr, evKV = nullptr, evRN = nullptr, evG1 = nullptr;
    if (!s2) {
        cudaStreamCreateWithFlags(&s2, cudaStreamNonBlocking);
        cudaStreamCreateWithFlags(&s3, cudaStreamNonBlocking);
        cudaEventCreateWithFlags(&evF,  cudaEventDisableTiming);
        cudaEventCreateWithFlags(&evKV, cudaEventDisableTiming);
        cudaEventCreateWithFlags(&evRN, cudaEventDisableTiming);
        cudaEventCreateWithFlags(&evG1, cudaEventDisableTiming);
        cudaFuncSetAttribute(mma_gemm<4, false, 1, 0>, cudaFuncAttributeMaxDynamicSharedMemorySize, smem_b(4, false, 1));
        cudaFuncSetAttribute(mma_gemm<4, false, 1, 1>, cudaFuncAttributeMaxDynamicSharedMemorySize, smem_b(4, false, 1));
        cudaFuncSetAttribute(mma_gemm<3, false, 1, 0>, cudaFuncAttributeMaxDynamicSharedMemorySize, smem_b(3, false, 1));
        cudaFuncSetAttribute(qk_gemm, cudaFuncAttributeMaxDynamicSharedMemorySize, SMEM_QK);
        cudaFuncSetAttribute(pv_gemm, cudaFuncAttributeMaxDynamicSharedMemorySize, SMEM_PV);
        cudaFuncSetAttribute(ov_gemm, cudaFuncAttributeMaxDynamicSharedMemorySize, SMEM_OV);
    }

    // ---- fork: KV path on s2 ----
    cudaEventRecord(evF, 0);
    cudaStreamWaitEvent(s2, evF, 0);

    mma_gemm<3, false, 1, 0><<<dim3(DQK / 96, SLEN / 128, 1), 256, smem_b(3, false, 1), s2>>>(
        hkv, W_kva, ckvraw, HID, HID, DQK, DQK, 0, 0, 0);
    build_K<<<SLEN, 128, 0, s2>>>(ckvraw, gkva, kvpos, Kch);
    transpose_hh<<<dim3(RKV / 32, SLEN / 32), dim3(32, 8), 0, s2>>>(Kch, ckvTh, SLEN, DQK);
    cudaEventRecord(evKV, s2);

    // ---- Q path head on default stream ----
    mma_gemm<4, false, 1, 0><<<dim3(RQ / 128, 2, 8), 256, smem_b(4, false, 1)>>>(
        hq, W_qa, part, HID / 8, HID, RQ, RQ,
        (long)(HID / 8), (long)(HID / 8) * RQ, (long)QLEN * RQ);
    reduce_rmsnorm<<<QLEN, 256>>>((const float4*)part, (float4*)qa, gqa);
    cudaEventRecord(evRN, 0);
    cudaStreamWaitEvent(s3, evRN, 0);

    // ---- per-head-group chains: step-3 half + attention (g0 stream 0, g1 s3) ----
    const long zb[2] = { 0, HGRP };
    cudaStream_t gs[2] = { (cudaStream_t)0, s3 };
    for (int grp = 0; grp < 2; grp++) {
        cudaStream_t st = gs[grp];
        const long z0 = zb[grp];
        const long qcol = z0 * (DNOPE + DROPE);
        const long qko = z0 * QLEN * DQK;
        const long po  = z0 * QLEN * SLEN;
        const long to  = z0 * QLEN * NTILES_S;
        const long ro  = z0 * QLEN;
        const long oo  = z0 * QLEN * RKV;

        // 3g) qfull[:, group cols] = qa @ W_qb[:, group cols]
        mma_gemm<4, false, 1, 0><<<dim3(HGRP * (DNOPE + DROPE) / 128, 2, 1), 256, smem_b(4, false, 1), st>>>(
            qa, W_qb + qcol, qfull + qcol, RQ, RQ, QB_COLS, QB_COLS, 0, 0, 0);

        // 6) Qch[:, :512] = q_nope @ q_absorb
        mma_gemm<4, false, 1, 1><<<dim3(RKV / 128, 2, HGRP), 256, smem_b(4, false, 1), st>>>(
            qfull + qcol, W_kvb + z0 * (long)(DNOPE + DNOPE) * RKV,
            (float*)(Qch + qko), DNOPE,
            QB_COLS, RKV, DQK,
            (long)(DNOPE + DROPE), (long)(DNOPE + DNOPE) * RKV, (long)QLEN * DQK);

        // 7) rope q_pe
        rope_Q<<<dim3(QLEN, HGRP), 32, 0, st>>>(
            qfull + qcol, qpos, Qch + qko);

        cudaStreamWaitEvent(st, evKV, 0);

        // 8) qk (k64 chunks)
        qk_gemm<<<dim3(SLEN / 128, QLEN / 128, HGRP), 256, SMEM_QK, st>>>(
            Qch + qko, Kch, P + po, scale, tmax + to, tsum + to);

        // 9) combine
        combine_stats<<<HGRP * QLEN / 8, dim3(32, 8), 0, st>>>(
            tmax + to, tsum + to, rowm + ro, rowis + ro);

        // 10) pv
        pv_gemm<<<dim3(RKV / 128, QLEN / 128, HGRP), 256, SMEM_PV, st>>>(
            P + po, ckvTh, och + oo, tmax + to, rowm + ro, rowis + ro);

        // 11) ov
        ov_gemm<<<dim3(1, 2, HGRP), 256, SMEM_OV, st>>>(
            och + oo, W_kvb + (long)DNOPE * RKV + z0 * (long)(DNOPE + DNOPE) * RKV,
            ao + z0 * DNOPE, (long)(DNOPE + DNOPE) * RKV);

        // 12a) partial out: ao[:, grp half] @ W_o[grp rows], split-K 2
        mma_gemm<4, false, 1, 0><<<dim3(HID / 128, 2, 2), 256, smem_b(4, false, 1), st>>>(
            ao + z0 * DNOPE, W_o + z0 * DNOPE * (long)HID, part + grp * 2 * (long)QLEN * HID,
            AO_COLS / 4, AO_COLS, HID, HID,
            (long)(AO_COLS / 4), (long)(AO_COLS / 4) * HID, (long)QLEN * HID);
    }
    cudaEventRecord(evG1, s3);
    cudaStreamWaitEvent(0, evG1, 0);

    // 12b) reduce 4 partial slices -> out
    reduce_slices<<<(QLEN * HID / 4 + 255) / 256, 256>>>((const float4*)part, (float4*)out, QLEN * HID / 4, 4);
}

// round 15
// speedup vs baseline: 1.0142x; 1.0142x over previous
#include <cuda_runtime.h>
#include <cuda_fp16.h>
#include <math.h>
#include <stdint.h>

// ---------------- Problem constants ----------------
#define NHEADS   128
#define DNOPE    128
#define DROPE    64
#define DQK      576
#define RKV      512
#define RQ       1536
#define HID      5120
#define QLEN     256
#define SLEN     4096
#define QB_COLS  24576
#define AO_COLS  16384
#define EPSF     1e-6f
#define NTILES_S (SLEN / 128)    // 32
#define HGRP     (NHEADS / 2)    // 64 heads per group

// ---------------- Scratch (device globals) ----------------
__device__ __align__(128) float  g_qa_buf [QLEN * RQ];
__device__ __align__(128) float  g_qfull  [QLEN * QB_COLS];
__device__ __align__(128) float  g_ckvraw [SLEN * DQK];
__device__ __align__(128) __half g_Kch    [SLEN * DQK];
__device__ __align__(128) __half g_ckvTh  [(size_t)RKV * SLEN];
__device__ __align__(128) __half g_Qch    [(size_t)NHEADS * QLEN * DQK];
__device__ __align__(128) __half g_P      [(size_t)NHEADS * QLEN * SLEN];  // 256 MB
__device__ __align__(128) __half g_och    [(size_t)NHEADS * QLEN * RKV];
__device__ __align__(128) float  g_ao     [QLEN * AO_COLS];
__device__ __align__(128) float  g_part   [8 * QLEN * HID];
__device__ __align__(128) float  g_rowm   [NHEADS * QLEN];
__device__ __align__(128) float  g_rowis  [NHEADS * QLEN];
__device__ __align__(128) float  g_tmax   [(size_t)NHEADS * QLEN * NTILES_S];
__device__ __align__(128) float  g_tsum   [(size_t)NHEADS * QLEN * NTILES_S];

// ---------------- helpers ----------------
__device__ __forceinline__ uint32_t smem_u32(const void* p) {
    uint32_t a;
    asm("{ .reg .u64 t; cvta.to.shared.u64 t, %1; cvt.u32.u64 %0, t; }" : "=r"(a) : "l"(p));
    return a;
}
__device__ __forceinline__ uint32_t f2tf(float x) {
    uint32_t r;
    asm("cvt.rna.tf32.f32 %0, %1;" : "=r"(r) : "f"(x));
    return r;
}
__device__ __forceinline__ uint32_t pack_bf16(float lo, float hi) {
    uint32_t r;
    asm("cvt.rn.bf16x2.f32 %0, %1, %2;" : "=r"(r) : "f"(hi), "f"(lo));
    return r;
}
__device__ __forceinline__ float bflo(uint32_t p) { return __uint_as_float(p << 16); }
__device__ __forceinline__ float bfhi(uint32_t p) { return __uint_as_float(p & 0xffff0000u); }

__device__ __forceinline__ void mma8(float* d, const uint32_t* a, uint32_t b0, uint32_t b1) {
    asm volatile(
        "mma.sync.aligned.m16n8k8.row.col.f32.tf32.tf32.f32 "
        "{%0,%1,%2,%3},{%4,%5,%6,%7},{%8,%9},{%0,%1,%2,%3};"
        : "+f"(d[0]), "+f"(d[1]), "+f"(d[2]), "+f"(d[3])
        : "r"(a[0]), "r"(a[1]), "r"(a[2]), "r"(a[3]), "r"(b0), "r"(b1));
}
__device__ __forceinline__ void mma16b(float* d, const uint32_t* a, uint32_t b0, uint32_t b1) {
    asm volatile(
        "mma.sync.aligned.m16n8k16.row.col.f32.bf16.bf16.f32 "
        "{%0,%1,%2,%3},{%4,%5,%6,%7},{%8,%9},{%0,%1,%2,%3};"
        : "+f"(d[0]), "+f"(d[1]), "+f"(d[2]), "+f"(d[3])
        : "r"(a[0]), "r"(a[1]), "r"(a[2]), "r"(a[3]), "r"(b0), "r"(b1));
}
__device__ __forceinline__ void mma16h(float* d, const uint32_t* a, uint32_t b0, uint32_t b1) {
    asm volatile(
        "mma.sync.aligned.m16n8k16.row.col.f32.f16.f16.f32 "
        "{%0,%1,%2,%3},{%4,%5,%6,%7},{%8,%9},{%0,%1,%2,%3};"
        : "+f"(d[0]), "+f"(d[1]), "+f"(d[2]), "+f"(d[3])
        : "r"(a[0]), "r"(a[1]), "r"(a[2]), "r"(a[3]), "r"(b0), "r"(b1));
}
__device__ __forceinline__ void ldm_x4(uint32_t* r, uint32_t addr) {
    asm volatile("ldmatrix.sync.aligned.m8n8.x4.shared.b16 {%0,%1,%2,%3}, [%4];"
                 : "=r"(r[0]), "=r"(r[1]), "=r"(r[2]), "=r"(r[3]) : "r"(addr));
}
__device__ __forceinline__ void cp16(uint32_t dst, const void* src) {
    asm volatile("cp.async.cg.shared.global [%0], [%1], 16;" :: "r"(dst), "l"(src) : "memory");
}
#define CP_COMMIT() asm volatile("cp.async.commit_group;" ::: "memory")
#define CP_WAIT(n)  asm volatile("cp.async.wait_group %0;" :: "n"(n) : "memory")

// ---------------- generic mma.sync GEMM (projections) ----------------
template<int NT, bool TRANSB, int PREC, int HOUT>
__global__ void __launch_bounds__(256, 2)
mma_gemm(const float* __restrict__ A, const float* __restrict__ B, float* __restrict__ C,
         int K, int lda, int ldb, int ldc, long sA, long sB, long sC)
{
    constexpr int BN   = NT * 32;
    constexpr int A_ST = (PREC == 0) ? 128 * 36 : 128 * 20 * 2;
    constexpr int B_ST = TRANSB ? ((PREC == 0) ? BN * 36 : BN * 20 * 2)
                                : ((PREC == 0) ? 32 * (BN + 8) : 16 * (BN + 8) * 2);
    constexpr int STG  = A_ST + B_ST;
    constexpr int BQ   = BN / 4;

    extern __shared__ uint32_t smu[];
    const uint32_t smem_base = smem_u32(smu);

    const int tid  = threadIdx.x;
    const int warp = tid >> 5;
    const int lane = tid & 31;
    const int wm = (warp >> 2) * 64;
    const int wn = (warp & 3) * (BN / 4);
    const int g  = lane >> 2;
    const int tq = lane & 3;

    const int bm = blockIdx.y * 128;
    const int bn = blockIdx.x * BN;
    A += (long)blockIdx.z * sA + (long)bm * lda;
    if (TRANSB) B += (long)blockIdx.z * sB + (long)bn * ldb;
    else        B += (long)blockIdx.z * sB + bn;
    const long coff = (long)blockIdx.z * sC + (long)bm * ldc + bn;

    const int NC = K >> 5;

    float acc[4][NT][4];
#pragma unroll
    for (int i = 0; i < 4; i++)
#pragma unroll
        for (int j = 0; j < NT; j++)
#pragma unroll
            for (int l = 0; l < 4; l++) acc[i][j][l] = 0.f;

    float4 rA[4];
    float4 rB[4];

    auto ldg_chunk = [&](int c) {
        const float* ga = A + c * 32;
#pragma unroll
        for (int i = 0; i < 4; i++) {
            int idx = tid + i * 256;
            int r = idx >> 3, c4 = (idx & 7) << 2;
            rA[i] = *(const float4*)(ga + (long)r * lda + c4);
        }
        if (TRANSB) {
            const float* gb = B + c * 32;
#pragma unroll
            for (int i = 0; i < NT; i++) {
                int idx = tid + i * 256;
                int r = idx >> 3, c4 = (idx & 7) << 2;
                rB[i] = *(const float4*)(gb + (long)r * ldb + c4);
            }
        } else if (PREC == 0) {
            const float* gb = B + (long)(c * 32) * ldb;
#pragma unroll
            for (int i = 0; i < NT; i++) {
                int idx = tid + i * 256;
                int r = idx / BQ, c4 = (idx % BQ) << 2;
                rB[i] = *(const float4*)(gb + (long)r * ldb + c4);
            }
        } else {
            const float* gb = B + (long)(c * 32) * ldb;
#pragma unroll
            for (int i = 0; i < 2; i++) {
                int u = tid + i * 256;
                if (u < 16 * BQ) {
                    int kp = u / BQ, c4 = (u % BQ) << 2;
                    rB[2 * i]     = *(const float4*)(gb + (long)(2 * kp) * ldb + c4);
                    rB[2 * i + 1] = *(const float4*)(gb + (long)(2 * kp + 1) * ldb + c4);
                }
            }
        }
    };

    auto sts_chunk = [&](int sbase) {
        uint32_t* sa = smu + sbase;
        uint32_t* sb = smu + sbase + A_ST;
        if (PREC == 0) {
#pragma unroll
            for (int i = 0; i < 4; i++) {
                int idx = tid + i * 256;
                int r = idx >> 3, c4 = (idx & 7) << 2;
                float4 v = rA[i];
                uint4 w = { f2tf(v.x), f2tf(v.y), f2tf(v.z), f2tf(v.w) };
                *(uint4*)&sa[r * 36 + c4] = w;
            }
            if (TRANSB) {
#pragma unroll
                for (int i = 0; i < NT; i++) {
                    int idx = tid + i * 256;
                    int r = idx >> 3, c4 = (idx & 7) << 2;
                    uint4 w = { f2tf(rB[i].x), f2tf(rB[i].y), f2tf(rB[i].z), f2tf(rB[i].w) };
                    *(uint4*)&sb[r * 36 + c4] = w;
                }
            } else {
#pragma unroll
                for (int i = 0; i < NT; i++) {
                    int idx = tid + i * 256;
                    int r = idx / BQ, c4 = (idx % BQ) << 2;
                    uint4 w = { f2tf(rB[i].x), f2tf(rB[i].y), f2tf(rB[i].z), f2tf(rB[i].w) };
                    *(uint4*)&sb[r * (BN + 8) + c4] = w;
                }
            }
        } else {
#pragma unroll
            for (int i = 0; i < 4; i++) {
                int idx = tid + i * 256;
                int r = idx >> 3, cu = (idx & 7) << 1;
                float4 v = rA[i];
                uint32_t h0 = pack_bf16(v.x, v.y), h1 = pack_bf16(v.z, v.w);
                uint32_t l0 = pack_bf16(v.x - bflo(h0), v.y - bfhi(h0));
                uint32_t l1 = pack_bf16(v.z - bflo(h1), v.w - bfhi(h1));
                *(uint2*)&sa[r * 20 + cu]            = make_uint2(h0, h1);
                *(uint2*)&sa[128 * 20 + r * 20 + cu] = make_uint2(l0, l1);
            }
            if (TRANSB) {
#pragma unroll
                for (int i = 0; i < NT; i++) {
                    int idx = tid + i * 256;
                    int r = idx >> 3, cu = (idx & 7) << 1;
                    float4 v = rB[i];
                    uint32_t h0 = pack_bf16(v.x, v.y), h1 = pack_bf16(v.z, v.w);
                    uint32_t l0 = pack_bf16(v.x - bflo(h0), v.y - bfhi(h0));
                    uint32_t l1 = pack_bf16(v.z - bflo(h1), v.w - bfhi(h1));
                    *(uint2*)&sb[r * 20 + cu]           = make_uint2(h0, h1);
                    *(uint2*)&sb[BN * 20 + r * 20 + cu] = make_uint2(l0, l1);
                }
            } else {
#pragma unroll
                for (int i = 0; i < 2; i++) {
                    int u = tid + i * 256;
                    if (u < 16 * BQ) {
                        int kp = u / BQ, c4 = (u % BQ) << 2;
                        float4 v0 = rB[2 * i], v1 = rB[2 * i + 1];
                        uint4 h = { pack_bf16(v0.x, v1.x), pack_bf16(v0.y, v1.y),
                                    pack_bf16(v0.z, v1.z), pack_bf16(v0.w, v1.w) };
                        uint4 l = { pack_bf16(v0.x - bflo(h.x), v1.x - bfhi(h.x)),
                                    pack_bf16(v0.y - bflo(h.y), v1.y - bfhi(h.y)),
                                    pack_bf16(v0.z - bflo(h.z), v1.z - bfhi(h.z)),
                                    pack_bf16(v0.w - bflo(h.w), v1.w - bfhi(h.w)) };
                        *(uint4*)&sb[kp * (BN + 8) + c4]                 = h;
                        *(uint4*)&sb[16 * (BN + 8) + kp * (BN + 8) + c4] = l;
                    }
                }
            }
        }
    };

    auto compute = [&](int sbase) {
        const uint32_t aB = smem_base + (uint32_t)sbase * 4;
        const uint32_t bB = smem_base + (uint32_t)(sbase + A_ST) * 4;
        const int mat = lane >> 3;
        if (PREC == 0) {
#pragma unroll
            for (int kk = 0; kk < 4; kk++) {
                const int kcu = kk * 8;
                uint32_t af[4][4];
#pragma unroll
                for (int mt = 0; mt < 4; mt++) {
                    int row = wm + mt * 16 + ((mat & 1) << 3) + (lane & 7);
                    int col = kcu + ((mat >> 1) << 2);
                    ldm_x4(af[mt], aB + (uint32_t)(row * 36 + col) * 4);
                }
                if (TRANSB) {
#pragma unroll
                    for (int np = 0; np < NT / 2; np++) {
                        uint32_t bf[4];
                        int row = wn + (2 * np + (mat >> 1)) * 8 + (lane & 7);
                        int col = kcu + ((mat & 1) << 2);
                        ldm_x4(bf, bB + (uint32_t)(row * 36 + col) * 4);
#pragma unroll
                        for (int mt = 0; mt < 4; mt++) {
                            mma8(acc[mt][2 * np],     af[mt], bf[0], bf[1]);
                            mma8(acc[mt][2 * np + 1], af[mt], bf[2], bf[3]);
                        }
                    }
                } else {
                    const uint32_t* sb = smu + sbase + A_ST;
#pragma unroll
                    for (int nt = 0; nt < NT; nt++) {
                        int n0 = wn + nt * 8 + g;
                        uint32_t b0 = sb[(kcu + tq) * (BN + 8) + n0];
                        uint32_t b1 = sb[(kcu + tq + 4) * (BN + 8) + n0];
#pragma unroll
                        for (int mt = 0; mt < 4; mt++)
                            mma8(acc[mt][nt], af[mt], b0, b1);
                    }
                }
            }
        } else {
#pragma unroll
            for (int kk = 0; kk < 2; kk++) {
                const int kcu = kk * 8;
                uint32_t ah[4][4], al[4][4];
#pragma unroll
                for (int mt = 0; mt < 4; mt++) {
                    int row = wm + mt * 16 + ((mat & 1) << 3) + (lane & 7);
                    int col = kcu + ((mat >> 1) << 2);
                    ldm_x4(ah[mt], aB + (uint32_t)(row * 20 + col) * 4);
                    ldm_x4(al[mt], aB + (uint32_t)(128 * 20 + row * 20 + col) * 4);
                }
                if (TRANSB) {
#pragma unroll
                    for (int np = 0; np < NT / 2; np++) {
                        uint32_t bh[4], bl[4];
                        int row = wn + (2 * np + (mat >> 1)) * 8 + (lane & 7);
                        int col = kcu + ((mat & 1) << 2);
                        ldm_x4(bh, bB + (uint32_t)(row * 20 + col) * 4);
                        ldm_x4(bl, bB + (uint32_t)(BN * 20 + row * 20 + col) * 4);
#pragma unroll
                        for (int mt = 0; mt < 4; mt++) {
                            mma16b(acc[mt][2 * np], ah[mt], bh[0], bh[1]);
                            mma16b(acc[mt][2 * np], al[mt], bh[0], bh[1]);
                            mma16b(acc[mt][2 * np], ah[mt], bl[0], bl[1]);
                            mma16b(acc[mt][2 * np + 1], ah[mt], bh[2], bh[3]);
                            mma16b(acc[mt][2 * np + 1], al[mt], bh[2], bh[3]);
                            mma16b(acc[mt][2 * np + 1], ah[mt], bl[2], bl[3]);
                        }
                    }
                } else {
                    const uint32_t* sbh = smu + sbase + A_ST;
                    const uint32_t* sbl = sbh + 16 * (BN + 8);
#pragma unroll
                    for (int nt = 0; nt < NT; nt++) {
                        int n0 = wn + nt * 8 + g;
                        uint32_t b0h = sbh[(kcu + tq) * (BN + 8) + n0];
                        uint32_t b1h = sbh[(kcu + tq + 4) * (BN + 8) + n0];
                        uint32_t b0l = sbl[(kcu + tq) * (BN + 8) + n0];
                        uint32_t b1l = sbl[(kcu + tq + 4) * (BN + 8) + n0];
#pragma unroll
                        for (int mt = 0; mt < 4; mt++) {
                            mma16b(acc[mt][nt], ah[mt], b0h, b1h);
                            mma16b(acc[mt][nt], al[mt], b0h, b1h);
                            mma16b(acc[mt][nt], ah[mt], b0l, b1l);
                        }
                    }
                }
            }
        }
    };

    ldg_chunk(0);
    sts_chunk(0);
    __syncthreads();
    for (int c = 0; c < NC; c++) {
        if (c + 1 < NC) ldg_chunk(c + 1);
        compute((c & 1) * STG);
        if (c + 1 < NC) {
            sts_chunk(((c + 1) & 1) * STG);
            __syncthreads();
        }
    }

    if (!HOUT) {
        float* Cf = C + coff;
#pragma unroll
        for (int mt = 0; mt < 4; mt++) {
            const int r0 = wm + mt * 16 + g;
#pragma unroll
            for (int nt = 0; nt < NT; nt++) {
                const int c0 = wn + nt * 8 + tq * 2;
                *(float2*)&Cf[(long)r0 * ldc + c0]       = make_float2(acc[mt][nt][0], acc[mt][nt][1]);
                *(float2*)&Cf[(long)(r0 + 8) * ldc + c0] = make_float2(acc[mt][nt][2], acc[mt][nt][3]);
            }
        }
    } else {
        __half* Ch = ((__half*)C) + coff;
#pragma unroll
        for (int mt = 0; mt < 4; mt++) {
            const int r0 = wm + mt * 16 + g;
#pragma unroll
            for (int nt = 0; nt < NT; nt++) {
                const int c0 = wn + nt * 8 + tq * 2;
                *(__half2*)&Ch[(long)r0 * ldc + c0]       = __floats2half2_rn(acc[mt][nt][0], acc[mt][nt][1]);
                *(__half2*)&Ch[(long)(r0 + 8) * ldc + c0] = __floats2half2_rn(acc[mt][nt][2], acc[mt][nt][3]);
            }
        }
    }
}

// ---------------- fp16 QK^T GEMM, cp.async 3-stage k32 chunks, fused exp + tile stats ----------------
__global__ void __launch_bounds__(256, 2)
qk_gemm(const __half* __restrict__ A, const __half* __restrict__ B, __half* __restrict__ Ph,
        float escale, float* __restrict__ gtmax, float* __restrict__ gtsum)
{
    constexpr int A_ST = 128 * 20;
    constexpr int B_ST = 128 * 20;
    constexpr int STG  = A_ST + B_ST;
    constexpr int NC   = DQK / 32;   // 18

    extern __shared__ uint32_t smu[];
    const uint32_t smem_base = smem_u32(smu);

    const int tid  = threadIdx.x;
    const int warp = tid >> 5;
    const int lane = tid & 31;
    const int wm = (warp >> 2) * 64;
    const int wn = (warp & 3) * 32;
    const int g  = lane >> 2;
    const int tq = lane & 3;
    const int mat = lane >> 3;

    const int bm = blockIdx.y * 128;
    const int bn = blockIdx.x * 128;
    const int z  = blockIdx.z;
    A  += (long)z * QLEN * DQK + (long)bm * DQK;
    B  += (long)bn * DQK;
    Ph += (long)z * QLEN * SLEN + (long)bm * SLEN + bn;

    float acc[4][4][4];
#pragma unroll
    for (int i = 0; i < 4; i++)
#pragma unroll
        for (int j = 0; j < 4; j++)
#pragma unroll
            for (int l = 0; l < 4; l++) acc[i][j][l] = 0.f;

    auto cp_chunk = [&](int c, int stg) {
        const uint32_t sa = smem_base + (uint32_t)(stg * STG) * 4;
        const uint32_t sb = sa + A_ST * 4;
        const __half* ga = A + c * 32;
        const __half* gb = B + c * 32;
#pragma unroll
        for (int i = 0; i < 2; i++) {
            int o = tid + i * 256;
            int r = o >> 2, cu = (o & 3) * 4;
            cp16(sa + (uint32_t)(r * 20 + cu) * 4, ga + (long)r * DQK + cu * 2);
            cp16(sb + (uint32_t)(r * 20 + cu) * 4, gb + (long)r * DQK + cu * 2);
        }
    };

    auto compute = [&](int stg) {
        const uint32_t aB = smem_base + (uint32_t)(stg * STG) * 4;
        const uint32_t bB = aB + A_ST * 4;
#pragma unroll
        for (int kk = 0; kk < 2; kk++) {
            const int kcu = kk * 8;
            uint32_t af[4][4];
#pragma unroll
            for (int mt = 0; mt < 4; mt++) {
                int row = wm + mt * 16 + ((mat & 1) << 3) + (lane & 7);
                int col = kcu + ((mat >> 1) << 2);
                ldm_x4(af[mt], aB + (uint32_t)(row * 20 + col) * 4);
            }
#pragma unroll
            for (int np = 0; np < 2; np++) {
                uint32_t bf[4];
                int row = wn + (2 * np + (mat >> 1)) * 8 + (lane & 7);
                int col = kcu + ((mat & 1) << 2);
                ldm_x4(bf, bB + (uint32_t)(row * 20 + col) * 4);
#pragma unroll
                for (int mt = 0; mt < 4; mt++) {
                    mma16h(acc[mt][2 * np],     af[mt], bf[0], bf[1]);
                    mma16h(acc[mt][2 * np + 1], af[mt], bf[2], bf[3]);
                }
            }
        }
    };

    cp_chunk(0, 0); CP_COMMIT();
    cp_chunk(1, 1); CP_COMMIT();
    for (int c = 0; c < NC; c++) {
        CP_WAIT(1);
        __syncthreads();
        if (c + 2 < NC) cp_chunk(c + 2, (c + 2) % 3);
        CP_COMMIT();
        compute(c % 3);
    }

    float* st_max = (float*)(smu + 3 * STG);
    float* st_sum = st_max + 512;
    const int nw = warp & 3;
    __syncthreads();
#pragma unroll
    for (int mt = 0; mt < 4; mt++) {
#pragma unroll
        for (int h = 0; h < 2; h++) {
            float mx = -INFINITY;
#pragma unroll
            for (int nt = 0; nt < 4; nt++) {
                mx = fmaxf(mx, acc[mt][nt][2 * h]);
                mx = fmaxf(mx, acc[mt][nt][2 * h + 1]);
            }
            mx = fmaxf(mx, __shfl_xor_sync(0xffffffffu, mx, 1));
            mx = fmaxf(mx, __shfl_xor_sync(0xffffffffu, mx, 2));
            if (tq == 0) st_max[(wm + mt * 16 + h * 8 + g) * 4 + nw] = mx * escale;
        }
    }
    __syncthreads();
#pragma unroll
    for (int mt = 0; mt < 4; mt++) {
#pragma unroll
        for (int h = 0; h < 2; h++) {
            const int row = wm + mt * 16 + h * 8 + g;
            float rm = fmaxf(fmaxf(st_max[row * 4 + 0], st_max[row * 4 + 1]),
                             fmaxf(st_max[row * 4 + 2], st_max[row * 4 + 3]));
            float s = 0.f;
#pragma unroll
            for (int nt = 0; nt < 4; nt++) {
                float p0 = __expf(fmaf(acc[mt][nt][2 * h],     escale, -rm));
                float p1 = __expf(fmaf(acc[mt][nt][2 * h + 1], escale, -rm));
                s += p0 + p1;
                *(__half2*)&Ph[(long)row * SLEN + wn + nt * 8 + tq * 2] =
                    __floats2half2_rn(p0, p1);
            }
            s += __shfl_xor_sync(0xffffffffu, s, 1);
            s += __shfl_xor_sync(0xffffffffu, s, 2);
            if (tq == 0) st_sum[row * 4 + nw] = s;
        }
    }
    __syncthreads();
    if (tid < 128) {
        float m = fmaxf(fmaxf(st_max[tid * 4 + 0], st_max[tid * 4 + 1]),
                        fmaxf(st_max[tid * 4 + 2], st_max[tid * 4 + 3]));
        float s = st_sum[tid * 4 + 0] + st_sum[tid * 4 + 1]
                + st_sum[tid * 4 + 2] + st_sum[tid * 4 + 3];
        long grow = (long)z * QLEN + bm + tid;
        gtmax[grow * NTILES_S + blockIdx.x] = m;
        gtsum[grow * NTILES_S + blockIdx.x] = s;
    }
}

// ---------------- fp16 PV GEMM, cp.async 3-stage k64 chunks, in-register rescale ----------------
__global__ void __launch_bounds__(256, 2)
pv_gemm(const __half* __restrict__ A, const __half* __restrict__ B, __half* __restrict__ C,
        const float* __restrict__ tmax, const float* __restrict__ rowm,
        const float* __restrict__ rowis)
{
    constexpr int A_ST = 128 * 36;
    constexpr int B_ST = 128 * 36;
    constexpr int STG  = A_ST + B_ST;
    constexpr int NC   = SLEN / 64;   // 64 chunks

    extern __shared__ uint32_t smu[];
    const uint32_t smem_base = smem_u32(smu);

    const int tid  = threadIdx.x;
    const int warp = tid >> 5;
    const int lane = tid & 31;
    const int wm = (warp >> 2) * 64;
    const int wn = (warp & 3) * 32;
    const int g  = lane >> 2;
    const int tq = lane & 3;
    const int mat = lane >> 3;

    const int bm = blockIdx.y * 128;
    const int bn = blockIdx.x * 128;
    const int z  = blockIdx.z;
    A += (long)z * QLEN * SLEN + (long)bm * SLEN;
    B += (long)bn * SLEN;
    C += (long)z * QLEN * RKV + (long)bm * RKV + bn;

    const long gbase = (long)z * QLEN + bm;
    float rm_[4][2], ris_[4][2];
#pragma unroll
    for (int mt = 0; mt < 4; mt++) {
        int r0 = wm + mt * 16 + g;
        rm_[mt][0]  = rowm[gbase + r0];
        rm_[mt][1]  = rowm[gbase + r0 + 8];
        ris_[mt][0] = rowis[gbase + r0];
        ris_[mt][1] = rowis[gbase + r0 + 8];
    }
    const float* tmax_b = tmax + gbase * NTILES_S;

    float acc[4][4][4];
#pragma unroll
    for (int i = 0; i < 4; i++)
#pragma unroll
        for (int j = 0; j < 4; j++)
#pragma unroll
            for (int l = 0; l < 4; l++) acc[i][j][l] = 0.f;

    uint32_t fac[4][2];

    auto upd_fac = [&](int tile) {
#pragma unroll
        for (int mt = 0; mt < 4; mt++) {
            int r0 = wm + mt * 16 + g;
            float f0 = __expf(tmax_b[(long)r0 * NTILES_S + tile] - rm_[mt][0]) * ris_[mt][0];
            float f1 = __expf(tmax_b[(long)(r0 + 8) * NTILES_S + tile] - rm_[mt][1]) * ris_[mt][1];
            __half2 h0 = __half2half2(__float2half_rn(f0));
            __half2 h1 = __half2half2(__float2half_rn(f1));
            fac[mt][0] = *(uint32_t*)&h0;
            fac[mt][1] = *(uint32_t*)&h1;
        }
    };

    auto cp_chunk = [&](int c, int stg) {
        const uint32_t sa = smem_base + (uint32_t)(stg * STG) * 4;
        const uint32_t sb = sa + A_ST * 4;
        const __half* ga = A + c * 64;
        const __half* gb = B + c * 64;
#pragma unroll
        for (int i = 0; i < 4; i++) {
            int o = tid + i * 256;
            int r = o >> 3, cu = (o & 7) * 4;
            cp16(sa + (uint32_t)(r * 36 + cu) * 4, ga + (long)r * SLEN + cu * 2);
            cp16(sb + (uint32_t)(r * 36 + cu) * 4, gb + (long)r * SLEN + cu * 2);
        }
    };

    auto compute = [&](int stg) {
        const uint32_t aB = smem_base + (uint32_t)(stg * STG) * 4;
        const uint32_t bB = aB + A_ST * 4;
#pragma unroll
        for (int kk = 0; kk < 4; kk++) {
            const int kcu = kk * 8;
            uint32_t af[4][4];
#pragma unroll
            for (int mt = 0; mt < 4; mt++) {
                int row = wm + mt * 16 + ((mat & 1) << 3) + (lane & 7);
                int col = kcu + ((mat >> 1) << 2);
                ldm_x4(af[mt], aB + (uint32_t)(row * 36 + col) * 4);
                __half2 f0 = *(__half2*)&fac[mt][0];
                __half2 f1 = *(__half2*)&fac[mt][1];
                *(__half2*)&af[mt][0] = __hmul2(*(__half2*)&af[mt][0], f0);
                *(__half2*)&af[mt][2] = __hmul2(*(__half2*)&af[mt][2], f0);
                *(__half2*)&af[mt][1] = __hmul2(*(__half2*)&af[mt][1], f1);
                *(__half2*)&af[mt][3] = __hmul2(*(__half2*)&af[mt][3], f1);
            }
#pragma unroll
            for (int np = 0; np < 2; np++) {
                uint32_t bf[4];
                int row = wn + (2 * np + (mat >> 1)) * 8 + (lane & 7);
                int col = kcu + ((mat & 1) << 2);
                ldm_x4(bf, bB + (uint32_t)(row * 36 + col) * 4);
#pragma unroll
                for (int mt = 0; mt < 4; mt++) {
                    mma16h(acc[mt][2 * np],     af[mt], bf[0], bf[1]);
                    mma16h(acc[mt][2 * np + 1], af[mt], bf[2], bf[3]);
                }
            }
        }
    };

    cp_chunk(0, 0); CP_COMMIT();
    cp_chunk(1, 1); CP_COMMIT();
    for (int c = 0; c < NC; c++) {
        CP_WAIT(1);
        __syncthreads();
        if (c + 2 < NC) cp_chunk(c + 2, (c + 2) % 3);
        CP_COMMIT();
        if ((c & 1) == 0) upd_fac(c >> 1);
        compute(c % 3);
    }

#pragma unroll
    for (int mt = 0; mt < 4; mt++) {
        const int r0 = wm + mt * 16 + g;
#pragma unroll
        for (int nt = 0; nt < 4; nt++) {
            const int c0 = wn + nt * 8 + tq * 2;
            *(__half2*)&C[(long)r0 * RKV + c0]       = __floats2half2_rn(acc[mt][nt][0], acc[mt][nt][1]);
            *(__half2*)&C[(long)(r0 + 8) * RKV + c0] = __floats2half2_rn(acc[mt][nt][2], acc[mt][nt][3]);
        }
    }
}

// ---------------- OV GEMM: ao[:, h*128:] = och[h] @ outabsorb[h]^T ----------------
__global__ void __launch_bounds__(256, 2)
ov_gemm(const __half* __restrict__ A, const float* __restrict__ B, float* __restrict__ C,
        long sB)
{
    constexpr int A_ST = 128 * 20;
    constexpr int B_ST = 2 * 128 * 20;
    constexpr int STG  = A_ST + B_ST;
    constexpr int NC   = RKV / 32;

    extern __shared__ uint32_t smu[];
    const uint32_t smem_base = smem_u32(smu);

    const int tid  = threadIdx.x;
    const int warp = tid >> 5;
    const int lane = tid & 31;
    const int wm = (warp >> 2) * 64;
    const int wn = (warp & 3) * 32;
    const int g  = lane >> 2;
    const int tq = lane & 3;
    const int mat = lane >> 3;

    const int bm = blockIdx.y * 128;
    const int z  = blockIdx.z;
    A += (long)z * QLEN * RKV + (long)bm * RKV;
    B += (long)z * sB;
    C += (long)z * DNOPE + (long)bm * AO_COLS;

    float acc[4][4][4];
#pragma unroll
    for (int i = 0; i < 4; i++)
#pragma unroll
        for (int j = 0; j < 4; j++)
#pragma unroll
            for (int l = 0; l < 4; l++) acc[i][j][l] = 0.f;

    float4 rB[4];

    auto cpA_chunk = [&](int c, int stg) {
        const uint32_t sa = smem_base + (uint32_t)(stg * STG) * 4;
        const __half* ga = A + c * 32;
#pragma unroll
        for (int i = 0; i < 2; i++) {
            int o = tid + i * 256;
            int r = o >> 2, cu = (o & 3) * 4;
            cp16(sa + (uint32_t)(r * 20 + cu) * 4, ga + (long)r * RKV + cu * 2);
        }
    };

    auto ldgB_chunk = [&](int c) {
        const float* gb = B + c * 32;
#pragma unroll
        for (int i = 0; i < 4; i++) {
            int o = tid + i * 256;
            int r = o >> 3, c4 = (o & 7) << 2;
            rB[i] = *(const float4*)(gb + (long)r * RKV + c4);
        }
    };

    auto stsB_chunk = [&](int stg) {
        uint32_t* sbh = smu + stg * STG + A_ST;
        uint32_t* sbl = sbh + 128 * 20;
#pragma unroll
        for (int i = 0; i < 4; i++) {
            int o = tid + i * 256;
            int r = o >> 3, cu = (o & 7) << 1;
            float4 v = rB[i];
            __half2 h0 = __floats2half2_rn(v.x, v.y);
            __half2 h1 = __floats2half2_rn(v.z, v.w);
            __half2 l0 = __floats2half2_rn(v.x - __half2float(h0.x), v.y - __half2float(h0.y));
            __half2 l1 = __floats2half2_rn(v.z - __half2float(h1.x), v.w - __half2float(h1.y));
            *(uint2*)&sbh[r * 20 + cu] = make_uint2(*(uint32_t*)&h0, *(uint32_t*)&h1);
            *(uint2*)&sbl[r * 20 + cu] = make_uint2(*(uint32_t*)&l0, *(uint32_t*)&l1);
        }
    };

    auto compute = [&](int stg) {
        const uint32_t aB  = smem_base + (uint32_t)(stg * STG) * 4;
        const uint32_t bBh = aB + A_ST * 4;
        const uint32_t bBl = bBh + 128 * 20 * 4;
#pragma unroll
        for (int kk = 0; kk < 2; kk++) {
            const int kcu = kk * 8;
            uint32_t af[4][4];
#pragma unroll
            for (int mt = 0; mt < 4; mt++) {
                int row = wm + mt * 16 + ((mat & 1) << 3) + (lane & 7);
                int col = kcu + ((mat >> 1) << 2);
                ldm_x4(af[mt], aB + (uint32_t)(row * 20 + col) * 4);
            }
#pragma unroll
            for (int np = 0; np < 2; np++) {
                uint32_t bh[4], bl[4];
                int row = wn + (2 * np + (mat >> 1)) * 8 + (lane & 7);
                int col = kcu + ((mat & 1) << 2);
                ldm_x4(bh, bBh + (uint32_t)(row * 20 + col) * 4);
                ldm_x4(bl, bBl + (uint32_t)(row * 20 + col) * 4);
#pragma unroll
                for (int mt = 0; mt < 4; mt++) {
                    mma16h(acc[mt][2 * np],     af[mt], bh[0], bh[1]);
                    mma16h(acc[mt][2 * np],     af[mt], bl[0], bl[1]);
                    mma16h(acc[mt][2 * np + 1], af[mt], bh[2], bh[3]);
                    mma16h(acc[mt][2 * np + 1], af[mt], bl[2], bl[3]);
                }
            }
        }
    };

    ldgB_chunk(0);
    cpA_chunk(0, 0); CP_COMMIT();
    stsB_chunk(0);
    CP_WAIT(0);
    __syncthreads();
    for (int c = 0; c < NC; c++) {
        if (c + 1 < NC) { ldgB_chunk(c + 1); cpA_chunk(c + 1, (c + 1) & 1); }
        CP_COMMIT();
        compute(c & 1);
        if (c + 1 < NC) {
            stsB_chunk((c + 1) & 1);
            CP_WAIT(0);
            __syncthreads();
        }
    }

#pragma unroll
    for (int mt = 0; mt < 4; mt++) {
        const int r0 = wm + mt * 16 + g;
#pragma unroll
        for (int nt = 0; nt < 4; nt++) {
            const int c0 = wn + nt * 8 + tq * 2;
            *(float2*)&C[(long)r0 * AO_COLS + c0]       = make_float2(acc[mt][nt][0], acc[mt][nt][1]);
            *(float2*)&C[(long)(r0 + 8) * AO_COLS + c0] = make_float2(acc[mt][nt][2], acc[mt][nt][3]);
        }
    }
}

// ---------------- Combine tile stats ----------------
__global__ void combine_stats(const float* __restrict__ tmax, const float* __restrict__ tsum,
                              float* __restrict__ rm, float* __restrict__ ris)
{
    const int row = blockIdx.x * 8 + threadIdx.y;
    const int t = threadIdx.x;
    float mv = tmax[(long)row * NTILES_S + t];
    float m = mv;
#pragma unroll
    for (int o = 16; o > 0; o >>= 1) m = fmaxf(m, __shfl_xor_sync(0xffffffffu, m, o));
    float s = tsum[(long)row * NTILES_S + t] * __expf(mv - m);
#pragma unroll
    for (int o = 16; o > 0; o >>= 1) s += __shfl_xor_sync(0xffffffffu, s, o);
    if (t == 0) { rm[row] = m; ris[row] = 1.f / s; }
}

// ---------------- Transpose half->half ----------------
__global__ void transpose_hh(const __half* __restrict__ in, __half* __restrict__ out,
                             int R, int ldin)
{
    __shared__ __half t[32][40];
    const int c0 = blockIdx.x * 32, r0 = blockIdx.y * 32;
    const int x = threadIdx.x, y0 = threadIdx.y;
    #pragma unroll
    for (int i = y0; i < 32; i += 8) t[i][x] = in[(long)(r0 + i) * ldin + c0 + x];
    __syncthreads();
    #pragma unroll
    for (int i = y0; i < 32; i += 8) out[(long)(c0 + i) * R + r0 + x] = t[x][i];
}

// ---------------- Split-K reduction ----------------
__global__ void reduce_slices(const float4* __restrict__ in, float4* __restrict__ out,
                              int n4, int S)
{
    int i = blockIdx.x * 256 + threadIdx.x;
    if (i >= n4) return;
    float4 a = in[i];
    for (int s = 1; s < S; s++) {
        float4 b = in[i + (long)s * n4];
        a.x += b.x; a.y += b.y; a.z += b.z; a.w += b.w;
    }
    out[i] = a;
}

// ---------------- Fused split-K reduce + RMSNorm for step 1 (16 slices) ----------------
__global__ void reduce_rmsnorm(const float4* __restrict__ in, float4* __restrict__ out,
                               const float* __restrict__ gw)
{
    const int row = blockIdx.x;
    const int tid = threadIdx.x;             // 256
    const int n4 = RQ / 4;                   // 384
    const int base = row * n4;
    float ss = 0.f;
    for (int c = tid; c < n4; c += 256) {
        float4 a = in[base + c];
#pragma unroll
        for (int s = 1; s < 16; s++) {
            float4 b = in[base + c + (long)s * QLEN * n4];
            a.x += b.x; a.y += b.y; a.z += b.z; a.w += b.w;
        }
        out[base + c] = a;
        ss += a.x * a.x + a.y * a.y + a.z * a.z + a.w * a.w;
    }
    __shared__ float red[256];
    red[tid] = ss; __syncthreads();
    for (int s = 128; s > 0; s >>= 1) { if (tid < s) red[tid] += red[tid + s]; __syncthreads(); }
    const float inv = rsqrtf(red[0] / (float)RQ + EPSF);
    for (int c = tid; c < n4; c += 256) {
        float4 v = out[base + c];
        float4 w = ((const float4*)gw)[c];
        v.x *= inv * w.x; v.y *= inv * w.y; v.z *= inv * w.z; v.w *= inv * w.w;
        out[base + c] = v;
    }
}

// ---------------- Build K_comb -> fp16 ----------------
__global__ void build_K(const float* __restrict__ raw, const float* __restrict__ g,
                        const int* __restrict__ kvpos, __half* __restrict__ Kh)
{
    const int s = blockIdx.x;
    const float* r = raw + (long)s * DQK;
    __half* k = Kh + (long)s * DQK;
    const int tid = threadIdx.x;

    float ss = 0.f;
    for (int c = tid; c < RKV / 4; c += 128) {
        float4 v = ((const float4*)r)[c];
        ss += v.x * v.x + v.y * v.y + v.z * v.z + v.w * v.w;
    }
    __shared__ float red[128];
    red[tid] = ss; __syncthreads();
    for (int st = 64; st > 0; st >>= 1) { if (tid < st) red[tid] += red[tid + st]; __syncthreads(); }
    const float inv = rsqrtf(red[0] / (float)RKV + EPSF);
    for (int c = tid; c < RKV / 4; c += 128) {
        float4 v = ((const float4*)r)[c];
        float4 w = ((const float4*)g)[c];
        __half2 h0 = __floats2half2_rn(v.x * inv * w.x, v.y * inv * w.y);
        __half2 h1 = __floats2half2_rn(v.z * inv * w.z, v.w * inv * w.w);
        *(__half2*)&k[c * 4]     = h0;
        *(__half2*)&k[c * 4 + 2] = h1;
    }

    if (tid < 32) {
        const int j = tid;
        const float x0 = r[RKV + 2 * j];
        const float x1 = r[RKV + 2 * j + 1];
        const float pos = (float)kvpos[s];
        const float invf = powf(10000.f, -(float)j / 32.f);
        float cs, sn; sincosf(pos * invf, &sn, &cs);
        k[RKV + j]      = __float2half_rn(x0 * cs - x1 * sn);
        k[RKV + 32 + j] = __float2half_rn(x0 * sn + x1 * cs);
    }
}

// ---------------- RoPE for q_pe -> fp16 ----------------
__global__ void rope_Q(const float* __restrict__ qfull, const int* __restrict__ qpos,
                       __half* __restrict__ Qh)
{
    const int t = blockIdx.x;
    const int h = blockIdx.y;
    const int j = threadIdx.x;
    const float* src = qfull + (long)t * QB_COLS + h * (DNOPE + DROPE) + DNOPE;
    const float x0 = src[2 * j];
    const float x1 = src[2 * j + 1];
    const float pos = (float)qpos[t];
    const float invf = powf(10000.f, -(float)j / 32.f);
    float cs, sn; sincosf(pos * invf, &sn, &cs);
    __half* dst = Qh + ((long)h * QLEN + t) * DQK + RKV;
    dst[j]      = __float2half_rn(x0 * cs - x1 * sn);
    dst[32 + j] = __float2half_rn(x0 * sn + x1 * cs);
}

// ---------------- Launch ----------------
static inline void* symv(const void* s)
{
    void* p = nullptr;
    cudaGetSymbolAddress(&p, s);
    return p;
}

static inline int smem_b(int NT, bool transb, int prec)
{
    int a = (prec == 0) ? 128 * 36 : 128 * 40;
    int b = transb ? ((prec == 0) ? NT * 32 * 36 : NT * 32 * 40)
                   : 32 * (NT * 32 + 8);
    return 2 * (a + b) * 4;
}
#define SMEM_PV (3 * (128 * 36 + 128 * 36) * 4)
#define SMEM_QK (3 * (128 * 20 + 128 * 20) * 4 + 4096)
#define SMEM_OV (2 * (128 * 20 + 2 * 128 * 20) * 4)

extern "C" void kernel_launch(void* const* d_in, const int* in_sizes, int n_in,
                              void* d_out, int out_size)
{
    const float* hq    = (const float*)d_in[0];
    const float* hkv   = (const float*)d_in[1];
    const float* W_qa  = (const float*)d_in[2];
    const float* gqa   = (const float*)d_in[3];
    const float* W_qb  = (const float*)d_in[4];
    const float* W_kva = (const float*)d_in[5];
    const float* gkva  = (const float*)d_in[6];
    const float* W_kvb = (const float*)d_in[7];
    const float* W_o   = (const float*)d_in[8];
    const int*   qpos  = (const int*)d_in[9];
    const int*   kvpos = (const int*)d_in[10];
    float*       out   = (float*)d_out;

    float*  qa     = (float*) symv(g_qa_buf);
    float*  qfull  = (float*) symv(g_qfull);
    float*  ckvraw = (float*) symv(g_ckvraw);
    __half* Kch    = (__half*)symv(g_Kch);
    __half* ckvTh  = (__half*)symv(g_ckvTh);
    __half* Qch    = (__half*)symv(g_Qch);
    __half* P      = (__half*)symv(g_P);
    __half* och    = (__half*)symv(g_och);
    float*  ao     = (float*) symv(g_ao);
    float*  part   = (float*) symv(g_part);
    float*  rowm   = (float*) symv(g_rowm);
    float*  rowis  = (float*) symv(g_rowis);
    float*  tmax   = (float*) symv(g_tmax);
    float*  tsum   = (float*) symv(g_tsum);

    const float scale = 1.0f / sqrtf(192.0f);

    static cudaStream_t s2 = nullptr, s3 = nullptr;
    static cudaEvent_t evF = nullptr, evKV = nullptr, evRN = nullptr, evG1 = nullptr;
    if (!s2) {
        cudaStreamCreateWithFlags(&s2, cudaStreamNonBlocking);
        cudaStreamCreateWithFlags(&s3, cudaStreamNonBlocking);
        cudaEventCreateWithFlags(&evF,  cudaEventDisableTiming);
        cudaEventCreateWithFlags(&evKV, cudaEventDisableTiming);
        cudaEventCreateWithFlags(&evRN, cudaEventDisableTiming);
        cudaEventCreateWithFlags(&evG1, cudaEventDisableTiming);
        cudaFuncSetAttribute(mma_gemm<4, false, 1, 0>, cudaFuncAttributeMaxDynamicSharedMemorySize, smem_b(4, false, 1));
        cudaFuncSetAttribute(mma_gemm<4, false, 1, 1>, cudaFuncAttributeMaxDynamicSharedMemorySize, smem_b(4, false, 1));
        cudaFuncSetAttribute(mma_gemm<3, false, 1, 0>, cudaFuncAttributeMaxDynamicSharedMemorySize, smem_b(3, false, 1));
        cudaFuncSetAttribute(qk_gemm, cudaFuncAttributeMaxDynamicSharedMemorySize, SMEM_QK);
        cudaFuncSetAttribute(pv_gemm, cudaFuncAttributeMaxDynamicSharedMemorySize, SMEM_PV);
        cudaFuncSetAttribute(ov_gemm, cudaFuncAttributeMaxDynamicSharedMemorySize, SMEM_OV);
    }

    // ---- fork: KV path on s2 ----
    cudaEventRecord(evF, 0);
    cudaStreamWaitEvent(s2, evF, 0);

    mma_gemm<3, false, 1, 0><<<dim3(DQK / 96, SLEN / 128, 1), 256, smem_b(3, false, 1), s2>>>(
        hkv, W_kva, ckvraw, HID, HID, DQK, DQK, 0, 0, 0);
    build_K<<<SLEN, 128, 0, s2>>>(ckvraw, gkva, kvpos, Kch);
    transpose_hh<<<dim3(RKV / 32, SLEN / 32), dim3(32, 8), 0, s2>>>(Kch, ckvTh, SLEN, DQK);
    cudaEventRecord(evKV, s2);

    // ---- Q path head on default stream ----
    // 1) qa = hq @ W_qa : split-K 16 (K/slice = 320)
    mma_gemm<4, false, 1, 0><<<dim3(RQ / 128, 2, 16), 256, smem_b(4, false, 1)>>>(
        hq, W_qa, part, HID / 16, HID, RQ, RQ,
        (long)(HID / 16), (long)(HID / 16) * RQ, (long)QLEN * RQ);
    reduce_rmsnorm<<<QLEN, 256>>>((const float4*)part, (float4*)qa, gqa);
    cudaEventRecord(evRN, 0);
    cudaStreamWaitEvent(s3, evRN, 0);

    // ---- per-head-group chains: step-3 half + attention (g0 stream 0, g1 s3) ----
    const long zb[2] = { 0, HGRP };
    cudaStream_t gs[2] = { (cudaStream_t)0, s3 };
    for (int grp = 0; grp < 2; grp++) {
        cudaStream_t st = gs[grp];
        const long z0 = zb[grp];
        const long qcol = z0 * (DNOPE + DROPE);
        const long qko = z0 * QLEN * DQK;
        const long po  = z0 * QLEN * SLEN;
        const long to  = z0 * QLEN * NTILES_S;
        const long ro  = z0 * QLEN;
        const long oo  = z0 * QLEN * RKV;

        // 3g) qfull[:, group cols] = qa @ W_qb[:, group cols]
        mma_gemm<4, false, 1, 0><<<dim3(HGRP * (DNOPE + DROPE) / 128, 2, 1), 256, smem_b(4, false, 1), st>>>(
            qa, W_qb + qcol, qfull + qcol, RQ, RQ, QB_COLS, QB_COLS, 0, 0, 0);

        // 6) Qch[:, :512] = q_nope @ q_absorb
        mma_gemm<4, false, 1, 1><<<dim3(RKV / 128, 2, HGRP), 256, smem_b(4, false, 1), st>>>(
            qfull + qcol, W_kvb + z0 * (long)(DNOPE + DNOPE) * RKV,
            (float*)(Qch + qko), DNOPE,
            QB_COLS, RKV, DQK,
            (long)(DNOPE + DROPE), (long)(DNOPE + DNOPE) * RKV, (long)QLEN * DQK);

        // 7) rope q_pe
        rope_Q<<<dim3(QLEN, HGRP), 32, 0, st>>>(
            qfull + qcol, qpos, Qch + qko);

        cudaStreamWaitEvent(st, evKV, 0);

        // 8) qk (k32 chunks, proven config)
        qk_gemm<<<dim3(SLEN / 128, QLEN / 128, HGRP), 256, SMEM_QK, st>>>(
            Qch + qko, Kch, P + po, scale, tmax + to, tsum + to);

        // 9) combine
        combine_stats<<<HGRP * QLEN / 8, dim3(32, 8), 0, st>>>(
            tmax + to, tsum + to, rowm + ro, rowis + ro);

        // 10) pv
        pv_gemm<<<dim3(RKV / 128, QLEN / 128, HGRP), 256, SMEM_PV, st>>>(
            P + po, ckvTh, och + oo, tmax + to, rowm + ro, rowis + ro);

        // 11) ov
        ov_gemm<<<dim3(1, 2, HGRP), 256, SMEM_OV, st>>>(
            och + oo, W_kvb + (long)DNOPE * RKV + z0 * (long)(DNOPE + DNOPE) * RKV,
            ao + z0 * DNOPE, (long)(DNOPE + DNOPE) * RKV);

        // 12a) partial out: ao[:, grp half] @ W_o[grp rows], split-K 2
        mma_gemm<4, false, 1, 0><<<dim3(HID / 128, 2, 2), 256, smem_b(4, false, 1), st>>>(
            ao + z0 * DNOPE, W_o + z0 * DNOPE * (long)HID, part + grp * 2 * (long)QLEN * HID,
            AO_COLS / 4, AO_COLS, HID, HID,
            (long)(AO_COLS / 4), (long)(AO_COLS / 4) * HID, (long)QLEN * HID);
    }
    cudaEventRecord(evG1, s3);
    cudaStreamWaitEvent(0, evG1, 0);

    // 12b) reduce 4 partial slices -> out
    reduce_slices<<<(QLEN * HID / 4 + 255) / 256, 256>>>((const float4*)part, (float4*)out, QLEN * HID / 4, 4);
}

// round 16
// speedup vs baseline: 1.0196x; 1.0053x over previous
#include <cuda_runtime.h>
#include <cuda_fp16.h>
#include <math.h>
#include <stdint.h>

// ---------------- Problem constants ----------------
#define NHEADS   128
#define DNOPE    128
#define DROPE    64
#define DQK      576
#define RKV      512
#define RQ       1536
#define HID      5120
#define QLEN     256
#define SLEN     4096
#define QB_COLS  24576
#define AO_COLS  16384
#define EPSF     1e-6f
#define NTILES_S (SLEN / 128)    // 32
#define HGRP     (NHEADS / 2)    // 64 heads per group

// ---------------- Scratch (device globals) ----------------
__device__ __align__(128) float  g_qa_buf [QLEN * RQ];
__device__ __align__(128) __half g_qfullh [QLEN * QB_COLS];
__device__ __align__(128) float  g_ckvraw [SLEN * DQK];
__device__ __align__(128) __half g_Kch    [SLEN * DQK];
__device__ __align__(128) __half g_ckvTh  [(size_t)RKV * SLEN];
__device__ __align__(128) __half g_Qch    [(size_t)NHEADS * QLEN * DQK];
__device__ __align__(128) __half g_P      [(size_t)NHEADS * QLEN * SLEN];  // 256 MB
__device__ __align__(128) __half g_och    [(size_t)NHEADS * QLEN * RKV];
__device__ __align__(128) float  g_ao     [QLEN * AO_COLS];
__device__ __align__(128) float  g_part   [16 * QLEN * RQ > 8 * QLEN * HID ? 16 * QLEN * RQ : 8 * QLEN * HID];
__device__ __align__(128) float  g_rowm   [NHEADS * QLEN];
__device__ __align__(128) float  g_rowis  [NHEADS * QLEN];
__device__ __align__(128) float  g_tmax   [(size_t)NHEADS * QLEN * NTILES_S];
__device__ __align__(128) float  g_tsum   [(size_t)NHEADS * QLEN * NTILES_S];

// ---------------- helpers ----------------
__device__ __forceinline__ uint32_t smem_u32(const void* p) {
    uint32_t a;
    asm("{ .reg .u64 t; cvta.to.shared.u64 t, %1; cvt.u32.u64 %0, t; }" : "=r"(a) : "l"(p));
    return a;
}
__device__ __forceinline__ uint32_t f2tf(float x) {
    uint32_t r;
    asm("cvt.rna.tf32.f32 %0, %1;" : "=r"(r) : "f"(x));
    return r;
}
__device__ __forceinline__ uint32_t pack_bf16(float lo, float hi) {
    uint32_t r;
    asm("cvt.rn.bf16x2.f32 %0, %1, %2;" : "=r"(r) : "f"(hi), "f"(lo));
    return r;
}
__device__ __forceinline__ float bflo(uint32_t p) { return __uint_as_float(p << 16); }
__device__ __forceinline__ float bfhi(uint32_t p) { return __uint_as_float(p & 0xffff0000u); }
__device__ __forceinline__ uint32_t pack_h2(float lo, float hi) {
    __half2 h = __floats2half2_rn(lo, hi);
    return *(uint32_t*)&h;
}
__device__ __forceinline__ float h2lo(uint32_t p) {
    __half h = *(__half*)&p;
    return __half2float(h);
}
__device__ __forceinline__ float h2hi(uint32_t p) {
    uint16_t u = (uint16_t)(p >> 16);
    __half h = *(__half*)&u;
    return __half2float(h);
}

__device__ __forceinline__ void mma8(float* d, const uint32_t* a, uint32_t b0, uint32_t b1) {
    asm volatile(
        "mma.sync.aligned.m16n8k8.row.col.f32.tf32.tf32.f32 "
        "{%0,%1,%2,%3},{%4,%5,%6,%7},{%8,%9},{%0,%1,%2,%3};"
        : "+f"(d[0]), "+f"(d[1]), "+f"(d[2]), "+f"(d[3])
        : "r"(a[0]), "r"(a[1]), "r"(a[2]), "r"(a[3]), "r"(b0), "r"(b1));
}
__device__ __forceinline__ void mma16b(float* d, const uint32_t* a, uint32_t b0, uint32_t b1) {
    asm volatile(
        "mma.sync.aligned.m16n8k16.row.col.f32.bf16.bf16.f32 "
        "{%0,%1,%2,%3},{%4,%5,%6,%7},{%8,%9},{%0,%1,%2,%3};"
        : "+f"(d[0]), "+f"(d[1]), "+f"(d[2]), "+f"(d[3])
        : "r"(a[0]), "r"(a[1]), "r"(a[2]), "r"(a[3]), "r"(b0), "r"(b1));
}
__device__ __forceinline__ void mma16h(float* d, const uint32_t* a, uint32_t b0, uint32_t b1) {
    asm volatile(
        "mma.sync.aligned.m16n8k16.row.col.f32.f16.f16.f32 "
        "{%0,%1,%2,%3},{%4,%5,%6,%7},{%8,%9},{%0,%1,%2,%3};"
        : "+f"(d[0]), "+f"(d[1]), "+f"(d[2]), "+f"(d[3])
        : "r"(a[0]), "r"(a[1]), "r"(a[2]), "r"(a[3]), "r"(b0), "r"(b1));
}
__device__ __forceinline__ void ldm_x4(uint32_t* r, uint32_t addr) {
    asm volatile("ldmatrix.sync.aligned.m8n8.x4.shared.b16 {%0,%1,%2,%3}, [%4];"
                 : "=r"(r[0]), "=r"(r[1]), "=r"(r[2]), "=r"(r[3]) : "r"(addr));
}
__device__ __forceinline__ void cp16(uint32_t dst, const void* src) {
    asm volatile("cp.async.cg.shared.global [%0], [%1], 16;" :: "r"(dst), "l"(src) : "memory");
}
#define CP_COMMIT() asm volatile("cp.async.commit_group;" ::: "memory")
#define CP_WAIT(n)  asm volatile("cp.async.wait_group %0;" :: "n"(n) : "memory")

// ---------------- generic mma.sync GEMM (projections) ----------------
// AH=1 (PREC=1, NN only): A is fp16 (exact, hi-only); B split to fp16 hi/lo; 2x mma16h.
template<int NT, bool TRANSB, int PREC, int HOUT, int AH>
__global__ void __launch_bounds__(256, 2)
mma_gemm(const float* __restrict__ A, const float* __restrict__ B, float* __restrict__ C,
         int K, int lda, int ldb, int ldc, long sA, long sB, long sC)
{
    constexpr int BN   = NT * 32;
    constexpr int A_ST = (PREC == 0) ? 128 * 36 : (AH ? 128 * 20 : 128 * 20 * 2);
    constexpr int B_ST = TRANSB ? ((PREC == 0) ? BN * 36 : BN * 20 * 2)
                                : ((PREC == 0) ? 32 * (BN + 8) : 16 * (BN + 8) * 2);
    constexpr int STG  = A_ST + B_ST;
    constexpr int BQ   = BN / 4;

    extern __shared__ uint32_t smu[];
    const uint32_t smem_base = smem_u32(smu);

    const int tid  = threadIdx.x;
    const int warp = tid >> 5;
    const int lane = tid & 31;
    const int wm = (warp >> 2) * 64;
    const int wn = (warp & 3) * (BN / 4);
    const int g  = lane >> 2;
    const int tq = lane & 3;

    const int bm = blockIdx.y * 128;
    const int bn = blockIdx.x * BN;
    const __half* Ah = (const __half*)A;
    if (AH) Ah += (long)blockIdx.z * sA + (long)bm * lda;
    else    A  += (long)blockIdx.z * sA + (long)bm * lda;
    if (TRANSB) B += (long)blockIdx.z * sB + (long)bn * ldb;
    else        B += (long)blockIdx.z * sB + bn;
    const long coff = (long)blockIdx.z * sC + (long)bm * ldc + bn;

    const int NC = K >> 5;

    float acc[4][NT][4];
#pragma unroll
    for (int i = 0; i < 4; i++)
#pragma unroll
        for (int j = 0; j < NT; j++)
#pragma unroll
            for (int l = 0; l < 4; l++) acc[i][j][l] = 0.f;

    float4 rA[4];
    uint2  rAh[4];
    float4 rB[4];

    auto ldg_chunk = [&](int c) {
        if (AH) {
            const __half* ga = Ah + c * 32;
#pragma unroll
            for (int i = 0; i < 4; i++) {
                int idx = tid + i * 256;
                int r = idx >> 3, c4 = (idx & 7) << 2;
                rAh[i] = *(const uint2*)(ga + (long)r * lda + c4);
            }
        } else {
            const float* ga = A + c * 32;
#pragma unroll
            for (int i = 0; i < 4; i++) {
                int idx = tid + i * 256;
                int r = idx >> 3, c4 = (idx & 7) << 2;
                rA[i] = *(const float4*)(ga + (long)r * lda + c4);
            }
        }
        if (TRANSB) {
            const float* gb = B + c * 32;
#pragma unroll
            for (int i = 0; i < NT; i++) {
                int idx = tid + i * 256;
                int r = idx >> 3, c4 = (idx & 7) << 2;
                rB[i] = *(const float4*)(gb + (long)r * ldb + c4);
            }
        } else if (PREC == 0) {
            const float* gb = B + (long)(c * 32) * ldb;
#pragma unroll
            for (int i = 0; i < NT; i++) {
                int idx = tid + i * 256;
                int r = idx / BQ, c4 = (idx % BQ) << 2;
                rB[i] = *(const float4*)(gb + (long)r * ldb + c4);
            }
        } else {
            const float* gb = B + (long)(c * 32) * ldb;
#pragma unroll
            for (int i = 0; i < 2; i++) {
                int u = tid + i * 256;
                if (u < 16 * BQ) {
                    int kp = u / BQ, c4 = (u % BQ) << 2;
                    rB[2 * i]     = *(const float4*)(gb + (long)(2 * kp) * ldb + c4);
                    rB[2 * i + 1] = *(const float4*)(gb + (long)(2 * kp + 1) * ldb + c4);
                }
            }
        }
    };

    auto sts_chunk = [&](int sbase) {
        uint32_t* sa = smu + sbase;
        uint32_t* sb = smu + sbase + A_ST;
        if (PREC == 0) {
#pragma unroll
            for (int i = 0; i < 4; i++) {
                int idx = tid + i * 256;
                int r = idx >> 3, c4 = (idx & 7) << 2;
                float4 v = rA[i];
                uint4 w = { f2tf(v.x), f2tf(v.y), f2tf(v.z), f2tf(v.w) };
                *(uint4*)&sa[r * 36 + c4] = w;
            }
            if (TRANSB) {
#pragma unroll
                for (int i = 0; i < NT; i++) {
                    int idx = tid + i * 256;
                    int r = idx >> 3, c4 = (idx & 7) << 2;
                    uint4 w = { f2tf(rB[i].x), f2tf(rB[i].y), f2tf(rB[i].z), f2tf(rB[i].w) };
                    *(uint4*)&sb[r * 36 + c4] = w;
                }
            } else {
#pragma unroll
                for (int i = 0; i < NT; i++) {
                    int idx = tid + i * 256;
                    int r = idx / BQ, c4 = (idx % BQ) << 2;
                    uint4 w = { f2tf(rB[i].x), f2tf(rB[i].y), f2tf(rB[i].z), f2tf(rB[i].w) };
                    *(uint4*)&sb[r * (BN + 8) + c4] = w;
                }
            }
        } else {
            if (AH) {
#pragma unroll
                for (int i = 0; i < 4; i++) {
                    int idx = tid + i * 256;
                    int r = idx >> 3, cu = (idx & 7) << 1;
                    *(uint2*)&sa[r * 20 + cu] = rAh[i];
                }
            } else {
#pragma unroll
                for (int i = 0; i < 4; i++) {
                    int idx = tid + i * 256;
                    int r = idx >> 3, cu = (idx & 7) << 1;
                    float4 v = rA[i];
                    uint32_t h0 = pack_bf16(v.x, v.y), h1 = pack_bf16(v.z, v.w);
                    uint32_t l0 = pack_bf16(v.x - bflo(h0), v.y - bfhi(h0));
                    uint32_t l1 = pack_bf16(v.z - bflo(h1), v.w - bfhi(h1));
                    *(uint2*)&sa[r * 20 + cu]            = make_uint2(h0, h1);
                    *(uint2*)&sa[128 * 20 + r * 20 + cu] = make_uint2(l0, l1);
                }
            }
            if (TRANSB) {
#pragma unroll
                for (int i = 0; i < NT; i++) {
                    int idx = tid + i * 256;
                    int r = idx >> 3, cu = (idx & 7) << 1;
                    float4 v = rB[i];
                    uint32_t h0 = pack_bf16(v.x, v.y), h1 = pack_bf16(v.z, v.w);
                    uint32_t l0 = pack_bf16(v.x - bflo(h0), v.y - bfhi(h0));
                    uint32_t l1 = pack_bf16(v.z - bflo(h1), v.w - bfhi(h1));
                    *(uint2*)&sb[r * 20 + cu]           = make_uint2(h0, h1);
                    *(uint2*)&sb[BN * 20 + r * 20 + cu] = make_uint2(l0, l1);
                }
            } else {
#pragma unroll
                for (int i = 0; i < 2; i++) {
                    int u = tid + i * 256;
                    if (u < 16 * BQ) {
                        int kp = u / BQ, c4 = (u % BQ) << 2;
                        float4 v0 = rB[2 * i], v1 = rB[2 * i + 1];
                        uint4 h, l;
                        if (AH) {
                            h = make_uint4(pack_h2(v0.x, v1.x), pack_h2(v0.y, v1.y),
                                           pack_h2(v0.z, v1.z), pack_h2(v0.w, v1.w));
                            l = make_uint4(pack_h2(v0.x - h2lo(h.x), v1.x - h2hi(h.x)),
                                           pack_h2(v0.y - h2lo(h.y), v1.y - h2hi(h.y)),
                                           pack_h2(v0.z - h2lo(h.z), v1.z - h2hi(h.z)),
                                           pack_h2(v0.w - h2lo(h.w), v1.w - h2hi(h.w)));
                        } else {
                            h = make_uint4(pack_bf16(v0.x, v1.x), pack_bf16(v0.y, v1.y),
                                           pack_bf16(v0.z, v1.z), pack_bf16(v0.w, v1.w));
                            l = make_uint4(pack_bf16(v0.x - bflo(h.x), v1.x - bfhi(h.x)),
                                           pack_bf16(v0.y - bflo(h.y), v1.y - bfhi(h.y)),
                                           pack_bf16(v0.z - bflo(h.z), v1.z - bfhi(h.z)),
                                           pack_bf16(v0.w - bflo(h.w), v1.w - bfhi(h.w)));
                        }
                        *(uint4*)&sb[kp * (BN + 8) + c4]                 = h;
                        *(uint4*)&sb[16 * (BN + 8) + kp * (BN + 8) + c4] = l;
                    }
                }
            }
        }
    };

    auto compute = [&](int sbase) {
        const uint32_t aB = smem_base + (uint32_t)sbase * 4;
        const uint32_t bB = smem_base + (uint32_t)(sbase + A_ST) * 4;
        const int mat = lane >> 3;
        if (PREC == 0) {
#pragma unroll
            for (int kk = 0; kk < 4; kk++) {
                const int kcu = kk * 8;
                uint32_t af[4][4];
#pragma unroll
                for (int mt = 0; mt < 4; mt++) {
                    int row = wm + mt * 16 + ((mat & 1) << 3) + (lane & 7);
                    int col = kcu + ((mat >> 1) << 2);
                    ldm_x4(af[mt], aB + (uint32_t)(row * 36 + col) * 4);
                }
                if (TRANSB) {
#pragma unroll
                    for (int np = 0; np < NT / 2; np++) {
                        uint32_t bf[4];
                        int row = wn + (2 * np + (mat >> 1)) * 8 + (lane & 7);
                        int col = kcu + ((mat & 1) << 2);
                        ldm_x4(bf, bB + (uint32_t)(row * 36 + col) * 4);
#pragma unroll
                        for (int mt = 0; mt < 4; mt++) {
                            mma8(acc[mt][2 * np],     af[mt], bf[0], bf[1]);
                            mma8(acc[mt][2 * np + 1], af[mt], bf[2], bf[3]);
                        }
                    }
                } else {
                    const uint32_t* sb = smu + sbase + A_ST;
#pragma unroll
                    for (int nt = 0; nt < NT; nt++) {
                        int n0 = wn + nt * 8 + g;
                        uint32_t b0 = sb[(kcu + tq) * (BN + 8) + n0];
                        uint32_t b1 = sb[(kcu + tq + 4) * (BN + 8) + n0];
#pragma unroll
                        for (int mt = 0; mt < 4; mt++)
                            mma8(acc[mt][nt], af[mt], b0, b1);
                    }
                }
            }
        } else {
#pragma unroll
            for (int kk = 0; kk < 2; kk++) {
                const int kcu = kk * 8;
                uint32_t ah[4][4], al[4][4];
#pragma unroll
                for (int mt = 0; mt < 4; mt++) {
                    int row = wm + mt * 16 + ((mat & 1) << 3) + (lane & 7);
                    int col = kcu + ((mat >> 1) << 2);
                    ldm_x4(ah[mt], aB + (uint32_t)(row * 20 + col) * 4);
                    if (!AH) ldm_x4(al[mt], aB + (uint32_t)(128 * 20 + row * 20 + col) * 4);
                }
                if (TRANSB) {
#pragma unroll
                    for (int np = 0; np < NT / 2; np++) {
                        uint32_t bh[4], bl[4];
                        int row = wn + (2 * np + (mat >> 1)) * 8 + (lane & 7);
                        int col = kcu + ((mat & 1) << 2);
                        ldm_x4(bh, bB + (uint32_t)(row * 20 + col) * 4);
                        ldm_x4(bl, bB + (uint32_t)(BN * 20 + row * 20 + col) * 4);
#pragma unroll
                        for (int mt = 0; mt < 4; mt++) {
                            mma16b(acc[mt][2 * np], ah[mt], bh[0], bh[1]);
                            mma16b(acc[mt][2 * np], al[mt], bh[0], bh[1]);
                            mma16b(acc[mt][2 * np], ah[mt], bl[0], bl[1]);
                            mma16b(acc[mt][2 * np + 1], ah[mt], bh[2], bh[3]);
                            mma16b(acc[mt][2 * np + 1], al[mt], bh[2], bh[3]);
                            mma16b(acc[mt][2 * np + 1], ah[mt], bl[2], bl[3]);
                        }
                    }
                } else {
                    const uint32_t* sbh = smu + sbase + A_ST;
                    const uint32_t* sbl = sbh + 16 * (BN + 8);
#pragma unroll
                    for (int nt = 0; nt < NT; nt++) {
                        int n0 = wn + nt * 8 + g;
                        uint32_t b0h = sbh[(kcu + tq) * (BN + 8) + n0];
                        uint32_t b1h = sbh[(kcu + tq + 4) * (BN + 8) + n0];
                        uint32_t b0l = sbl[(kcu + tq) * (BN + 8) + n0];
                        uint32_t b1l = sbl[(kcu + tq + 4) * (BN + 8) + n0];
#pragma unroll
                        for (int mt = 0; mt < 4; mt++) {
                            if (AH) {
                                mma16h(acc[mt][nt], ah[mt], b0h, b1h);
                                mma16h(acc[mt][nt], ah[mt], b0l, b1l);
                            } else {
                                mma16b(acc[mt][nt], ah[mt], b0h, b1h);
                                mma16b(acc[mt][nt], al[mt], b0h, b1h);
                                mma16b(acc[mt][nt], ah[mt], b0l, b1l);
                            }
                        }
                    }
                }
            }
        }
    };

    ldg_chunk(0);
    sts_chunk(0);
    __syncthreads();
    for (int c = 0; c < NC; c++) {
        if (c + 1 < NC) ldg_chunk(c + 1);
        compute((c & 1) * STG);
        if (c + 1 < NC) {
            sts_chunk(((c + 1) & 1) * STG);
            __syncthreads();
        }
    }

    if (!HOUT) {
        float* Cf = C + coff;
#pragma unroll
        for (int mt = 0; mt < 4; mt++) {
            const int r0 = wm + mt * 16 + g;
#pragma unroll
            for (int nt = 0; nt < NT; nt++) {
                const int c0 = wn + nt * 8 + tq * 2;
                *(float2*)&Cf[(long)r0 * ldc + c0]       = make_float2(acc[mt][nt][0], acc[mt][nt][1]);
                *(float2*)&Cf[(long)(r0 + 8) * ldc + c0] = make_float2(acc[mt][nt][2], acc[mt][nt][3]);
            }
        }
    } else {
        __half* Ch = ((__half*)C) + coff;
#pragma unroll
        for (int mt = 0; mt < 4; mt++) {
            const int r0 = wm + mt * 16 + g;
#pragma unroll
            for (int nt = 0; nt < NT; nt++) {
                const int c0 = wn + nt * 8 + tq * 2;
                *(__half2*)&Ch[(long)r0 * ldc + c0]       = __floats2half2_rn(acc[mt][nt][0], acc[mt][nt][1]);
                *(__half2*)&Ch[(long)(r0 + 8) * ldc + c0] = __floats2half2_rn(acc[mt][nt][2], acc[mt][nt][3]);
            }
        }
    }
}

// ---------------- fp16 QK^T GEMM, cp.async 3-stage k32 chunks, fused exp + tile stats ----------------
__global__ void __launch_bounds__(256, 2)
qk_gemm(const __half* __restrict__ A, const __half* __restrict__ B, __half* __restrict__ Ph,
        float escale, float* __restrict__ gtmax, float* __restrict__ gtsum)
{
    constexpr int A_ST = 128 * 20;
    constexpr int B_ST = 128 * 20;
    constexpr int STG  = A_ST + B_ST;
    constexpr int NC   = DQK / 32;   // 18

    extern __shared__ uint32_t smu[];
    const uint32_t smem_base = smem_u32(smu);

    const int tid  = threadIdx.x;
    const int warp = tid >> 5;
    const int lane = tid & 31;
    const int wm = (warp >> 2) * 64;
    const int wn = (warp & 3) * 32;
    const int g  = lane >> 2;
    const int tq = lane & 3;
    const int mat = lane >> 3;

    const int bm = blockIdx.y * 128;
    const int bn = blockIdx.x * 128;
    const int z  = blockIdx.z;
    A  += (long)z * QLEN * DQK + (long)bm * DQK;
    B  += (long)bn * DQK;
    Ph += (long)z * QLEN * SLEN + (long)bm * SLEN + bn;

    float acc[4][4][4];
#pragma unroll
    for (int i = 0; i < 4; i++)
#pragma unroll
        for (int j = 0; j < 4; j++)
#pragma unroll
            for (int l = 0; l < 4; l++) acc[i][j][l] = 0.f;

    auto cp_chunk = [&](int c, int stg) {
        const uint32_t sa = smem_base + (uint32_t)(stg * STG) * 4;
        const uint32_t sb = sa + A_ST * 4;
        const __half* ga = A + c * 32;
        const __half* gb = B + c * 32;
#pragma unroll
        for (int i = 0; i < 2; i++) {
            int o = tid + i * 256;
            int r = o >> 2, cu = (o & 3) * 4;
            cp16(sa + (uint32_t)(r * 20 + cu) * 4, ga + (long)r * DQK + cu * 2);
            cp16(sb + (uint32_t)(r * 20 + cu) * 4, gb + (long)r * DQK + cu * 2);
        }
    };

    auto compute = [&](int stg) {
        const uint32_t aB = smem_base + (uint32_t)(stg * STG) * 4;
        const uint32_t bB = aB + A_ST * 4;
#pragma unroll
        for (int kk = 0; kk < 2; kk++) {
            const int kcu = kk * 8;
            uint32_t af[4][4];
#pragma unroll
            for (int mt = 0; mt < 4; mt++) {
                int row = wm + mt * 16 + ((mat & 1) << 3) + (lane & 7);
                int col = kcu + ((mat >> 1) << 2);
                ldm_x4(af[mt], aB + (uint32_t)(row * 20 + col) * 4);
            }
#pragma unroll
            for (int np = 0; np < 2; np++) {
                uint32_t bf[4];
                int row = wn + (2 * np + (mat >> 1)) * 8 + (lane & 7);
                int col = kcu + ((mat & 1) << 2);
                ldm_x4(bf, bB + (uint32_t)(row * 20 + col) * 4);
#pragma unroll
                for (int mt = 0; mt < 4; mt++) {
                    mma16h(acc[mt][2 * np],     af[mt], bf[0], bf[1]);
                    mma16h(acc[mt][2 * np + 1], af[mt], bf[2], bf[3]);
                }
            }
        }
    };

    cp_chunk(0, 0); CP_COMMIT();
    cp_chunk(1, 1); CP_COMMIT();
    for (int c = 0; c < NC; c++) {
        CP_WAIT(1);
        __syncthreads();
        if (c + 2 < NC) cp_chunk(c + 2, (c + 2) % 3);
        CP_COMMIT();
        compute(c % 3);
    }

    float* st_max = (float*)(smu + 3 * STG);
    float* st_sum = st_max + 512;
    const int nw = warp & 3;
    __syncthreads();
#pragma unroll
    for (int mt = 0; mt < 4; mt++) {
#pragma unroll
        for (int h = 0; h < 2; h++) {
            float mx = -INFINITY;
#pragma unroll
            for (int nt = 0; nt < 4; nt++) {
                mx = fmaxf(mx, acc[mt][nt][2 * h]);
                mx = fmaxf(mx, acc[mt][nt][2 * h + 1]);
            }
            mx = fmaxf(mx, __shfl_xor_sync(0xffffffffu, mx, 1));
            mx = fmaxf(mx, __shfl_xor_sync(0xffffffffu, mx, 2));
            if (tq == 0) st_max[(wm + mt * 16 + h * 8 + g) * 4 + nw] = mx * escale;
        }
    }
    __syncthreads();
#pragma unroll
    for (int mt = 0; mt < 4; mt++) {
#pragma unroll
        for (int h = 0; h < 2; h++) {
            const int row = wm + mt * 16 + h * 8 + g;
            float rm = fmaxf(fmaxf(st_max[row * 4 + 0], st_max[row * 4 + 1]),
                             fmaxf(st_max[row * 4 + 2], st_max[row * 4 + 3]));
            float s = 0.f;
#pragma unroll
            for (int nt = 0; nt < 4; nt++) {
                float p0 = __expf(fmaf(acc[mt][nt][2 * h],     escale, -rm));
                float p1 = __expf(fmaf(acc[mt][nt][2 * h + 1], escale, -rm));
                s += p0 + p1;
                *(__half2*)&Ph[(long)row * SLEN + wn + nt * 8 + tq * 2] =
                    __floats2half2_rn(p0, p1);
            }
            s += __shfl_xor_sync(0xffffffffu, s, 1);
            s += __shfl_xor_sync(0xffffffffu, s, 2);
            if (tq == 0) st_sum[row * 4 + nw] = s;
        }
    }
    __syncthreads();
    if (tid < 128) {
        float m = fmaxf(fmaxf(st_max[tid * 4 + 0], st_max[tid * 4 + 1]),
                        fmaxf(st_max[tid * 4 + 2], st_max[tid * 4 + 3]));
        float s = st_sum[tid * 4 + 0] + st_sum[tid * 4 + 1]
                + st_sum[tid * 4 + 2] + st_sum[tid * 4 + 3];
        long grow = (long)z * QLEN + bm + tid;
        gtmax[grow * NTILES_S + blockIdx.x] = m;
        gtsum[grow * NTILES_S + blockIdx.x] = s;
    }
}

// ---------------- fp16 PV GEMM, cp.async 3-stage k64 chunks, in-register rescale ----------------
__global__ void __launch_bounds__(256, 2)
pv_gemm(const __half* __restrict__ A, const __half* __restrict__ B, __half* __restrict__ C,
        const float* __restrict__ tmax, const float* __restrict__ rowm,
        const float* __restrict__ rowis)
{
    constexpr int A_ST = 128 * 36;
    constexpr int B_ST = 128 * 36;
    constexpr int STG  = A_ST + B_ST;
    constexpr int NC   = SLEN / 64;

    extern __shared__ uint32_t smu[];
    const uint32_t smem_base = smem_u32(smu);

    const int tid  = threadIdx.x;
    const int warp = tid >> 5;
    const int lane = tid & 31;
    const int wm = (warp >> 2) * 64;
    const int wn = (warp & 3) * 32;
    const int g  = lane >> 2;
    const int tq = lane & 3;
    const int mat = lane >> 3;

    const int bm = blockIdx.y * 128;
    const int bn = blockIdx.x * 128;
    const int z  = blockIdx.z;
    A += (long)z * QLEN * SLEN + (long)bm * SLEN;
    B += (long)bn * SLEN;
    C += (long)z * QLEN * RKV + (long)bm * RKV + bn;

    const long gbase = (long)z * QLEN + bm;
    float rm_[4][2], ris_[4][2];
#pragma unroll
    for (int mt = 0; mt < 4; mt++) {
        int r0 = wm + mt * 16 + g;
        rm_[mt][0]  = rowm[gbase + r0];
        rm_[mt][1]  = rowm[gbase + r0 + 8];
        ris_[mt][0] = rowis[gbase + r0];
        ris_[mt][1] = rowis[gbase + r0 + 8];
    }
    const float* tmax_b = tmax + gbase * NTILES_S;

    float acc[4][4][4];
#pragma unroll
    for (int i = 0; i < 4; i++)
#pragma unroll
        for (int j = 0; j < 4; j++)
#pragma unroll
            for (int l = 0; l < 4; l++) acc[i][j][l] = 0.f;

    uint32_t fac[4][2];

    auto upd_fac = [&](int tile) {
#pragma unroll
        for (int mt = 0; mt < 4; mt++) {
            int r0 = wm + mt * 16 + g;
            float f0 = __expf(tmax_b[(long)r0 * NTILES_S + tile] - rm_[mt][0]) * ris_[mt][0];
            float f1 = __expf(tmax_b[(long)(r0 + 8) * NTILES_S + tile] - rm_[mt][1]) * ris_[mt][1];
            __half2 h0 = __half2half2(__float2half_rn(f0));
            __half2 h1 = __half2half2(__float2half_rn(f1));
            fac[mt][0] = *(uint32_t*)&h0;
            fac[mt][1] = *(uint32_t*)&h1;
        }
    };

    auto cp_chunk = [&](int c, int stg) {
        const uint32_t sa = smem_base + (uint32_t)(stg * STG) * 4;
        const uint32_t sb = sa + A_ST * 4;
        const __half* ga = A + c * 64;
        const __half* gb = B + c * 64;
#pragma unroll
        for (int i = 0; i < 4; i++) {
            int o = tid + i * 256;
            int r = o >> 3, cu = (o & 7) * 4;
            cp16(sa + (uint32_t)(r * 36 + cu) * 4, ga + (long)r * SLEN + cu * 2);
            cp16(sb + (uint32_t)(r * 36 + cu) * 4, gb + (long)r * SLEN + cu * 2);
        }
    };

    auto compute = [&](int stg) {
        const uint32_t aB = smem_base + (uint32_t)(stg * STG) * 4;
        const uint32_t bB = aB + A_ST * 4;
#pragma unroll
        for (int kk = 0; kk < 4; kk++) {
            const int kcu = kk * 8;
            uint32_t af[4][4];
#pragma unroll
            for (int mt = 0; mt < 4; mt++) {
                int row = wm + mt * 16 + ((mat & 1) << 3) + (lane & 7);
                int col = kcu + ((mat >> 1) << 2);
                ldm_x4(af[mt], aB + (uint32_t)(row * 36 + col) * 4);
                __half2 f0 = *(__half2*)&fac[mt][0];
                __half2 f1 = *(__half2*)&fac[mt][1];
                *(__half2*)&af[mt][0] = __hmul2(*(__half2*)&af[mt][0], f0);
                *(__half2*)&af[mt][2] = __hmul2(*(__half2*)&af[mt][2], f0);
                *(__half2*)&af[mt][1] = __hmul2(*(__half2*)&af[mt][1], f1);
                *(__half2*)&af[mt][3] = __hmul2(*(__half2*)&af[mt][3], f1);
            }
#pragma unroll
            for (int np = 0; np < 2; np++) {
                uint32_t bf[4];
                int row = wn + (2 * np + (mat >> 1)) * 8 + (lane & 7);
                int col = kcu + ((mat & 1) << 2);
                ldm_x4(bf, bB + (uint32_t)(row * 36 + col) * 4);
#pragma unroll
                for (int mt = 0; mt < 4; mt++) {
                    mma16h(acc[mt][2 * np],     af[mt], bf[0], bf[1]);
                    mma16h(acc[mt][2 * np + 1], af[mt], bf[2], bf[3]);
                }
            }
        }
    };

    cp_chunk(0, 0); CP_COMMIT();
    cp_chunk(1, 1); CP_COMMIT();
    for (int c = 0; c < NC; c++) {
        CP_WAIT(1);
        __syncthreads();
        if (c + 2 < NC) cp_chunk(c + 2, (c + 2) % 3);
        CP_COMMIT();
        if ((c & 1) == 0) upd_fac(c >> 1);
        compute(c % 3);
    }

#pragma unroll
    for (int mt = 0; mt < 4; mt++) {
        const int r0 = wm + mt * 16 + g;
#pragma unroll
        for (int nt = 0; nt < 4; nt++) {
            const int c0 = wn + nt * 8 + tq * 2;
            *(__half2*)&C[(long)r0 * RKV + c0]       = __floats2half2_rn(acc[mt][nt][0], acc[mt][nt][1]);
            *(__half2*)&C[(long)(r0 + 8) * RKV + c0] = __floats2half2_rn(acc[mt][nt][2], acc[mt][nt][3]);
        }
    }
}

// ---------------- OV GEMM ----------------
__global__ void __launch_bounds__(256, 2)
ov_gemm(const __half* __restrict__ A, const float* __restrict__ B, float* __restrict__ C,
        long sB)
{
    constexpr int A_ST = 128 * 20;
    constexpr int B_ST = 2 * 128 * 20;
    constexpr int STG  = A_ST + B_ST;
    constexpr int NC   = RKV / 32;

    extern __shared__ uint32_t smu[];
    const uint32_t smem_base = smem_u32(smu);

    const int tid  = threadIdx.x;
    const int warp = tid >> 5;
    const int lane = tid & 31;
    const int wm = (warp >> 2) * 64;
    const int wn = (warp & 3) * 32;
    const int g  = lane >> 2;
    const int tq = lane & 3;
    const int mat = lane >> 3;

    const int bm = blockIdx.y * 128;
    const int z  = blockIdx.z;
    A += (long)z * QLEN * RKV + (long)bm * RKV;
    B += (long)z * sB;
    C += (long)z * DNOPE + (long)bm * AO_COLS;

    float acc[4][4][4];
#pragma unroll
    for (int i = 0; i < 4; i++)
#pragma unroll
        for (int j = 0; j < 4; j++)
#pragma unroll
            for (int l = 0; l < 4; l++) acc[i][j][l] = 0.f;

    float4 rB[4];

    auto cpA_chunk = [&](int c, int stg) {
        const uint32_t sa = smem_base + (uint32_t)(stg * STG) * 4;
        const __half* ga = A + c * 32;
#pragma unroll
        for (int i = 0; i < 2; i++) {
            int o = tid + i * 256;
            int r = o >> 2, cu = (o & 3) * 4;
            cp16(sa + (uint32_t)(r * 20 + cu) * 4, ga + (long)r * RKV + cu * 2);
        }
    };

    auto ldgB_chunk = [&](int c) {
        const float* gb = B + c * 32;
#pragma unroll
        for (int i = 0; i < 4; i++) {
            int o = tid + i * 256;
            int r = o >> 3, c4 = (o & 7) << 2;
            rB[i] = *(const float4*)(gb + (long)r * RKV + c4);
        }
    };

    auto stsB_chunk = [&](int stg) {
        uint32_t* sbh = smu + stg * STG + A_ST;
        uint32_t* sbl = sbh + 128 * 20;
#pragma unroll
        for (int i = 0; i < 4; i++) {
            int o = tid + i * 256;
            int r = o >> 3, cu = (o & 7) << 1;
            float4 v = rB[i];
            __half2 h0 = __floats2half2_rn(v.x, v.y);
            __half2 h1 = __floats2half2_rn(v.z, v.w);
            __half2 l0 = __floats2half2_rn(v.x - __half2float(h0.x), v.y - __half2float(h0.y));
            __half2 l1 = __floats2half2_rn(v.z - __half2float(h1.x), v.w - __half2float(h1.y));
            *(uint2*)&sbh[r * 20 + cu] = make_uint2(*(uint32_t*)&h0, *(uint32_t*)&h1);
            *(uint2*)&sbl[r * 20 + cu] = make_uint2(*(uint32_t*)&l0, *(uint32_t*)&l1);
        }
    };

    auto compute = [&](int stg) {
        const uint32_t aB  = smem_base + (uint32_t)(stg * STG) * 4;
        const uint32_t bBh = aB + A_ST * 4;
        const uint32_t bBl = bBh + 128 * 20 * 4;
#pragma unroll
        for (int kk = 0; kk < 2; kk++) {
            const int kcu = kk * 8;
            uint32_t af[4][4];
#pragma unroll
            for (int mt = 0; mt < 4; mt++) {
                int row = wm + mt * 16 + ((mat & 1) << 3) + (lane & 7);
                int col = kcu + ((mat >> 1) << 2);
                ldm_x4(af[mt], aB + (uint32_t)(row * 20 + col) * 4);
            }
#pragma unroll
            for (int np = 0; np < 2; np++) {
                uint32_t bh[4], bl[4];
                int row = wn + (2 * np + (mat >> 1)) * 8 + (lane & 7);
                int col = kcu + ((mat & 1) << 2);
                ldm_x4(bh, bBh + (uint32_t)(row * 20 + col) * 4);
                ldm_x4(bl, bBl + (uint32_t)(row * 20 + col) * 4);
#pragma unroll
                for (int mt = 0; mt < 4; mt++) {
                    mma16h(acc[mt][2 * np],     af[mt], bh[0], bh[1]);
                    mma16h(acc[mt][2 * np],     af[mt], bl[0], bl[1]);
                    mma16h(acc[mt][2 * np + 1], af[mt], bh[2], bh[3]);
                    mma16h(acc[mt][2 * np + 1], af[mt], bl[2], bl[3]);
                }
            }
        }
    };

    ldgB_chunk(0);
    cpA_chunk(0, 0); CP_COMMIT();
    stsB_chunk(0);
    CP_WAIT(0);
    __syncthreads();
    for (int c = 0; c < NC; c++) {
        if (c + 1 < NC) { ldgB_chunk(c + 1); cpA_chunk(c + 1, (c + 1) & 1); }
        CP_COMMIT();
        compute(c & 1);
        if (c + 1 < NC) {
            stsB_chunk((c + 1) & 1);
            CP_WAIT(0);
            __syncthreads();
        }
    }

#pragma unroll
    for (int mt = 0; mt < 4; mt++) {
        const int r0 = wm + mt * 16 + g;
#pragma unroll
        for (int nt = 0; nt < 4; nt++) {
            const int c0 = wn + nt * 8 + tq * 2;
            *(float2*)&C[(long)r0 * AO_COLS + c0]       = make_float2(acc[mt][nt][0], acc[mt][nt][1]);
            *(float2*)&C[(long)(r0 + 8) * AO_COLS + c0] = make_float2(acc[mt][nt][2], acc[mt][nt][3]);
        }
    }
}

// ---------------- Combine tile stats ----------------
__global__ void combine_stats(const float* __restrict__ tmax, const float* __restrict__ tsum,
                              float* __restrict__ rm, float* __restrict__ ris)
{
    const int row = blockIdx.x * 8 + threadIdx.y;
    const int t = threadIdx.x;
    float mv = tmax[(long)row * NTILES_S + t];
    float m = mv;
#pragma unroll
    for (int o = 16; o > 0; o >>= 1) m = fmaxf(m, __shfl_xor_sync(0xffffffffu, m, o));
    float s = tsum[(long)row * NTILES_S + t] * __expf(mv - m);
#pragma unroll
    for (int o = 16; o > 0; o >>= 1) s += __shfl_xor_sync(0xffffffffu, s, o);
    if (t == 0) { rm[row] = m; ris[row] = 1.f / s; }
}

// ---------------- Transpose half->half ----------------
__global__ void transpose_hh(const __half* __restrict__ in, __half* __restrict__ out,
                             int R, int ldin)
{
    __shared__ __half t[32][40];
    const int c0 = blockIdx.x * 32, r0 = blockIdx.y * 32;
    const int x = threadIdx.x, y0 = threadIdx.y;
    #pragma unroll
    for (int i = y0; i < 32; i += 8) t[i][x] = in[(long)(r0 + i) * ldin + c0 + x];
    __syncthreads();
    #pragma unroll
    for (int i = y0; i < 32; i += 8) out[(long)(c0 + i) * R + r0 + x] = t[x][i];
}

// ---------------- Split-K reduction ----------------
__global__ void reduce_slices(const float4* __restrict__ in, float4* __restrict__ out,
                              int n4, int S)
{
    int i = blockIdx.x * 256 + threadIdx.x;
    if (i >= n4) return;
    float4 a = in[i];
    for (int s = 1; s < S; s++) {
        float4 b = in[i + (long)s * n4];
        a.x += b.x; a.y += b.y; a.z += b.z; a.w += b.w;
    }
    out[i] = a;
}

// ---------------- Fused split-K reduce + RMSNorm for step 1 (16 slices) ----------------
__global__ void reduce_rmsnorm(const float4* __restrict__ in, float4* __restrict__ out,
                               const float* __restrict__ gw)
{
    const int row = blockIdx.x;
    const int tid = threadIdx.x;
    const int n4 = RQ / 4;
    const int base = row * n4;
    float ss = 0.f;
    for (int c = tid; c < n4; c += 256) {
        float4 a = in[base + c];
#pragma unroll
        for (int s = 1; s < 16; s++) {
            float4 b = in[base + c + (long)s * QLEN * n4];
            a.x += b.x; a.y += b.y; a.z += b.z; a.w += b.w;
        }
        out[base + c] = a;
        ss += a.x * a.x + a.y * a.y + a.z * a.z + a.w * a.w;
    }
    __shared__ float red[256];
    red[tid] = ss; __syncthreads();
    for (int s = 128; s > 0; s >>= 1) { if (tid < s) red[tid] += red[tid + s]; __syncthreads(); }
    const float inv = rsqrtf(red[0] / (float)RQ + EPSF);
    for (int c = tid; c < n4; c += 256) {
        float4 v = out[base + c];
        float4 w = ((const float4*)gw)[c];
        v.x *= inv * w.x; v.y *= inv * w.y; v.z *= inv * w.z; v.w *= inv * w.w;
        out[base + c] = v;
    }
}

// ---------------- Build K_comb -> fp16 ----------------
__global__ void build_K(const float* __restrict__ raw, const float* __restrict__ g,
                        const int* __restrict__ kvpos, __half* __restrict__ Kh)
{
    const int s = blockIdx.x;
    const float* r = raw + (long)s * DQK;
    __half* k = Kh + (long)s * DQK;
    const int tid = threadIdx.x;

    float ss = 0.f;
    for (int c = tid; c < RKV / 4; c += 128) {
        float4 v = ((const float4*)r)[c];
        ss += v.x * v.x + v.y * v.y + v.z * v.z + v.w * v.w;
    }
    __shared__ float red[128];
    red[tid] = ss; __syncthreads();
    for (int st = 64; st > 0; st >>= 1) { if (tid < st) red[tid] += red[tid + st]; __syncthreads(); }
    const float inv = rsqrtf(red[0] / (float)RKV + EPSF);
    for (int c = tid; c < RKV / 4; c += 128) {
        float4 v = ((const float4*)r)[c];
        float4 w = ((const float4*)g)[c];
        __half2 h0 = __floats2half2_rn(v.x * inv * w.x, v.y * inv * w.y);
        __half2 h1 = __floats2half2_rn(v.z * inv * w.z, v.w * inv * w.w);
        *(__half2*)&k[c * 4]     = h0;
        *(__half2*)&k[c * 4 + 2] = h1;
    }

    if (tid < 32) {
        const int j = tid;
        const float x0 = r[RKV + 2 * j];
        const float x1 = r[RKV + 2 * j + 1];
        const float pos = (float)kvpos[s];
        const float invf = powf(10000.f, -(float)j / 32.f);
        float cs, sn; sincosf(pos * invf, &sn, &cs);
        k[RKV + j]      = __float2half_rn(x0 * cs - x1 * sn);
        k[RKV + 32 + j] = __float2half_rn(x0 * sn + x1 * cs);
    }
}

// ---------------- RoPE for q_pe (fp16 in) -> fp16 ----------------
__global__ void rope_Q(const __half* __restrict__ qfull, const int* __restrict__ qpos,
                       __half* __restrict__ Qh)
{
    const int t = blockIdx.x;
    const int h = blockIdx.y;
    const int j = threadIdx.x;
    const __half* src = qfull + (long)t * QB_COLS + h * (DNOPE + DROPE) + DNOPE;
    const float x0 = __half2float(src[2 * j]);
    const float x1 = __half2float(src[2 * j + 1]);
    const float pos = (float)qpos[t];
    const float invf = powf(10000.f, -(float)j / 32.f);
    float cs, sn; sincosf(pos * invf, &sn, &cs);
    __half* dst = Qh + ((long)h * QLEN + t) * DQK + RKV;
    dst[j]      = __float2half_rn(x0 * cs - x1 * sn);
    dst[32 + j] = __float2half_rn(x0 * sn + x1 * cs);
}

// ---------------- Launch ----------------
static inline void* symv(const void* s)
{
    void* p = nullptr;
    cudaGetSymbolAddress(&p, s);
    return p;
}

static inline int smem_b(int NT, bool transb, int prec, int ah = 0)
{
    int a = (prec == 0) ? 128 * 36 : (ah ? 128 * 20 : 128 * 40);
    int b = transb ? ((prec == 0) ? NT * 32 * 36 : NT * 32 * 40)
                   : 32 * (NT * 32 + 8);
    return 2 * (a + b) * 4;
}
#define SMEM_PV (3 * (128 * 36 + 128 * 36) * 4)
#define SMEM_QK (3 * (128 * 20 + 128 * 20) * 4 + 4096)
#define SMEM_OV (2 * (128 * 20 + 2 * 128 * 20) * 4)

extern "C" void kernel_launch(void* const* d_in, const int* in_sizes, int n_in,
                              void* d_out, int out_size)
{
    const float* hq    = (const float*)d_in[0];
    const float* hkv   = (const float*)d_in[1];
    const float* W_qa  = (const float*)d_in[2];
    const float* gqa   = (const float*)d_in[3];
    const float* W_qb  = (const float*)d_in[4];
    const float* W_kva = (const float*)d_in[5];
    const float* gkva  = (const float*)d_in[6];
    const float* W_kvb = (const float*)d_in[7];
    const float* W_o   = (const float*)d_in[8];
    const int*   qpos  = (const int*)d_in[9];
    const int*   kvpos = (const int*)d_in[10];
    float*       out   = (float*)d_out;

    float*  qa     = (float*) symv(g_qa_buf);
    __half* qfullh = (__half*)symv(g_qfullh);
    float*  ckvraw = (float*) symv(g_ckvraw);
    __half* Kch    = (__half*)symv(g_Kch);
    __half* ckvTh  = (__half*)symv(g_ckvTh);
    __half* Qch    = (__half*)symv(g_Qch);
    __half* P      = (__half*)symv(g_P);
    __half* och    = (__half*)symv(g_och);
    float*  ao     = (float*) symv(g_ao);
    float*  part   = (float*) symv(g_part);
    float*  rowm   = (float*) symv(g_rowm);
    float*  rowis  = (float*) symv(g_rowis);
    float*  tmax   = (float*) symv(g_tmax);
    float*  tsum   = (float*) symv(g_tsum);

    const float scale = 1.0f / sqrtf(192.0f);

    static cudaStream_t s2 = nullptr, s3 = nullptr;
    static cudaEvent_t evF = nullptr, evKV = nullptr, evRN = nullptr, evG1 = nullptr;
    if (!s2) {
        cudaStreamCreateWithFlags(&s2, cudaStreamNonBlocking);
        cudaStreamCreateWithFlags(&s3, cudaStreamNonBlocking);
        cudaEventCreateWithFlags(&evF,  cudaEventDisableTiming);
        cudaEventCreateWithFlags(&evKV, cudaEventDisableTiming);
        cudaEventCreateWithFlags(&evRN, cudaEventDisableTiming);
        cudaEventCreateWithFlags(&evG1, cudaEventDisableTiming);
        cudaFuncSetAttribute(mma_gemm<4, false, 1, 0, 0>, cudaFuncAttributeMaxDynamicSharedMemorySize, smem_b(4, false, 1));
        cudaFuncSetAttribute(mma_gemm<4, false, 1, 1, 0>, cudaFuncAttributeMaxDynamicSharedMemorySize, smem_b(4, false, 1));
        cudaFuncSetAttribute(mma_gemm<4, false, 1, 1, 1>, cudaFuncAttributeMaxDynamicSharedMemorySize, smem_b(4, false, 1, 1));
        cudaFuncSetAttribute(mma_gemm<3, false, 1, 0, 0>, cudaFuncAttributeMaxDynamicSharedMemorySize, smem_b(3, false, 1));
        cudaFuncSetAttribute(qk_gemm, cudaFuncAttributeMaxDynamicSharedMemorySize, SMEM_QK);
        cudaFuncSetAttribute(pv_gemm, cudaFuncAttributeMaxDynamicSharedMemorySize, SMEM_PV);
        cudaFuncSetAttribute(ov_gemm, cudaFuncAttributeMaxDynamicSharedMemorySize, SMEM_OV);
    }

    // ---- fork: KV path on s2 ----
    cudaEventRecord(evF, 0);
    cudaStreamWaitEvent(s2, evF, 0);

    mma_gemm<3, false, 1, 0, 0><<<dim3(DQK / 96, SLEN / 128, 1), 256, smem_b(3, false, 1), s2>>>(
        hkv, W_kva, ckvraw, HID, HID, DQK, DQK, 0, 0, 0);
    build_K<<<SLEN, 128, 0, s2>>>(ckvraw, gkva, kvpos, Kch);
    transpose_hh<<<dim3(RKV / 32, SLEN / 32), dim3(32, 8), 0, s2>>>(Kch, ckvTh, SLEN, DQK);
    cudaEventRecord(evKV, s2);

    // ---- Q path head on default stream ----
    mma_gemm<4, false, 1, 0, 0><<<dim3(RQ / 128, 2, 16), 256, smem_b(4, false, 1)>>>(
        hq, W_qa, part, HID / 16, HID, RQ, RQ,
        (long)(HID / 16), (long)(HID / 16) * RQ, (long)QLEN * RQ);
    reduce_rmsnorm<<<QLEN, 256>>>((const float4*)part, (float4*)qa, gqa);
    cudaEventRecord(evRN, 0);
    cudaStreamWaitEvent(s3, evRN, 0);

    // ---- per-head-group chains (g0 stream 0, g1 s3) ----
    const long zb[2] = { 0, HGRP };
    cudaStream_t gs[2] = { (cudaStream_t)0, s3 };
    for (int grp = 0; grp < 2; grp++) {
        cudaStream_t st = gs[grp];
        const long z0 = zb[grp];
        const long qcol = z0 * (DNOPE + DROPE);
        const long qko = z0 * QLEN * DQK;
        const long po  = z0 * QLEN * SLEN;
        const long to  = z0 * QLEN * NTILES_S;
        const long ro  = z0 * QLEN;
        const long oo  = z0 * QLEN * RKV;

        // 3g) qfullh[:, group cols] = qa @ W_qb[:, group cols]  [fp16 out]
        mma_gemm<4, false, 1, 1, 0><<<dim3(HGRP * (DNOPE + DROPE) / 128, 2, 1), 256, smem_b(4, false, 1), st>>>(
            qa, W_qb + qcol, (float*)(qfullh + qcol), RQ, RQ, QB_COLS, QB_COLS, 0, 0, 0);

        // 6) Qch[:, :512] = q_nope(fp16) @ q_absorb  [AH: fp16 A, fp16-split B, 2x mma]
        mma_gemm<4, false, 1, 1, 1><<<dim3(RKV / 128, 2, HGRP), 256, smem_b(4, false, 1, 1), st>>>(
            (const float*)(qfullh + qcol), W_kvb + z0 * (long)(DNOPE + DNOPE) * RKV,
            (float*)(Qch + qko), DNOPE,
            QB_COLS, RKV, DQK,
            (long)(DNOPE + DROPE), (long)(DNOPE + DNOPE) * RKV, (long)QLEN * DQK);

        // 7) rope q_pe
        rope_Q<<<dim3(QLEN, HGRP), 32, 0, st>>>(
            qfullh + qcol, qpos, Qch + qko);

        cudaStreamWaitEvent(st, evKV, 0);

        // 8) qk
        qk_gemm<<<dim3(SLEN / 128, QLEN / 128, HGRP), 256, SMEM_QK, st>>>(
            Qch + qko, Kch, P + po, scale, tmax + to, tsum + to);

        // 9) combine
        combine_stats<<<HGRP * QLEN / 8, dim3(32, 8), 0, st>>>(
            tmax + to, tsum + to, rowm + ro, rowis + ro);

        // 10) pv
        pv_gemm<<<dim3(RKV / 128, QLEN / 128, HGRP), 256, SMEM_PV, st>>>(
            P + po, ckvTh, och + oo, tmax + to, rowm + ro, rowis + ro);

        // 11) ov
        ov_gemm<<<dim3(1, 2, HGRP), 256, SMEM_OV, st>>>(
            och + oo, W_kvb + (long)DNOPE * RKV + z0 * (long)(DNOPE + DNOPE) * RKV,
            ao + z0 * DNOPE, (long)(DNOPE + DNOPE) * RKV);

        // 12a) partial out
        mma_gemm<4, false, 1, 0, 0><<<dim3(HID / 128, 2, 2), 256, smem_b(4, false, 1), st>>>(
            ao + z0 * DNOPE, W_o + z0 * DNOPE * (long)HID, part + grp * 2 * (long)QLEN * HID,
            AO_COLS / 4, AO_COLS, HID, HID,
            (long)(AO_COLS / 4), (long)(AO_COLS / 4) * HID, (long)QLEN * HID);
    }
    cudaEventRecord(evG1, s3);
    cudaStreamWaitEvent(0, evG1, 0);

    // 12b) reduce 4 partial slices -> out
    reduce_slices<<<(QLEN * HID / 4 + 255) / 256, 256>>>((const float4*)part, (float4*)out, QLEN * HID / 4, 4);
}